// round 13
// baseline (speedup 1.0000x reference)
#include <cuda_runtime.h>
#include <cuda_bf16.h>
#include <math.h>

#define BB   2
#define NN   2048
#define HH   256
#define NH   8
#define HD   32
#define WIN  32
#define WLEN 65
#define BN   (BB*NN)                       /* 4096 rows */
#define AOFF ((size_t)BB*NN*4*HH)          /* x_final elements = 4194304 */

// ---------------- scratch (static device globals; no allocation) ------------
__device__ __align__(16) float g_q[BN*HH];
__device__ __align__(16) float g_k[BN*HH];
__device__ __align__(16) float g_v[BN*HH];
__device__ __align__(16) float g_vd[BN*HH];
__device__ __align__(16) float g_vn[BN*HH];
__device__ __align__(16) float g_xout[BN*HH];
__device__ __align__(16) float g_vaggr[BN*3*HH];
// bf16 packed (2 per unsigned word)
__device__ __align__(16) unsigned g_bx[BN*4*HH/2];      // whole x tensor
__device__ __align__(16) unsigned g_bWq[HH*HH/2];
__device__ __align__(16) unsigned g_bWk[HH*HH/2];
__device__ __align__(16) unsigned g_bWv[HH*HH/2];
__device__ __align__(16) unsigned g_bWvec[HH*2*HH/2];
__device__ __align__(16) unsigned g_bWo[HH*3*HH/2];
__device__ __align__(16) unsigned g_bWg[2*HH*HH/2];
__device__ __align__(16) unsigned g_bxout[BN*HH/2];
__device__ __align__(16) unsigned g_bvd[BN*HH/2];
__device__ __align__(16) unsigned g_bvn[BN*HH/2];

// ---------------- helpers ----------------------------------------------------
__device__ __forceinline__ unsigned pk(float lo, float hi) {
    unsigned r; asm("cvt.rn.bf16x2.f32 %0, %1, %2;" : "=r"(r) : "f"(hi), "f"(lo));
    return r;
}
__device__ __forceinline__ unsigned su(const void* p) {
    return (unsigned)__cvta_generic_to_shared(p);
}
__device__ __forceinline__ void cpa16(unsigned saddr, const void* gptr) {
    asm volatile("cp.async.ca.shared.global [%0], [%1], 16;" :: "r"(saddr), "l"(gptr));
}
#define CPA_COMMIT asm volatile("cp.async.commit_group;" ::: "memory")
#define CPA_WAIT0  asm volatile("cp.async.wait_group 0;"  ::: "memory")
__device__ __forceinline__ void ldsm4(unsigned* r, unsigned a) {
    asm volatile("ldmatrix.sync.aligned.m8n8.x4.shared.b16 {%0,%1,%2,%3},[%4];"
        : "=r"(r[0]), "=r"(r[1]), "=r"(r[2]), "=r"(r[3]) : "r"(a));
}
__device__ __forceinline__ void ldsm4t(unsigned* r, unsigned a) {
    asm volatile("ldmatrix.sync.aligned.m8n8.x4.trans.shared.b16 {%0,%1,%2,%3},[%4];"
        : "=r"(r[0]), "=r"(r[1]), "=r"(r[2]), "=r"(r[3]) : "r"(a));
}
__device__ __forceinline__ void mma_bf16(float* c, const unsigned* a, const unsigned* b) {
    asm volatile("mma.sync.aligned.m16n8k16.row.col.f32.bf16.bf16.f32 "
        "{%0,%1,%2,%3},{%4,%5,%6,%7},{%8,%9},{%0,%1,%2,%3};"
        : "+f"(c[0]), "+f"(c[1]), "+f"(c[2]), "+f"(c[3])
        : "r"(a[0]), "r"(a[1]), "r"(a[2]), "r"(a[3]), "r"(b[0]), "r"(b[1]));
}

// ---------------- kernel 0: bf16 prepack -------------------------------------
// words: x 2097152 | Wq 32768 | Wk 32768 | Wv 32768 | Wvec 65536 | Wo 98304 | Wg 65536
__global__ __launch_bounds__(256) void prep_bf16(
    const float* __restrict__ x,
    const float* __restrict__ Wq, const float* __restrict__ Wk,
    const float* __restrict__ Wv, const float* __restrict__ Wvec,
    const float* __restrict__ Wo, const float* __restrict__ Wg)
{
    const int tid = blockIdx.x * 256 + threadIdx.x;     // grid 1024 -> 262144 thr
    for (int w = tid; w < 2424832; w += 262144) {
        const float* src; unsigned* dst; int off;
        if (w < 2097152) { src = x; dst = g_bx; off = w; }
        else {
            int u = w - 2097152;
            if      (u <  32768) { src = Wq;   dst = g_bWq;   off = u; }
            else if (u <  65536) { src = Wk;   dst = g_bWk;   off = u -  32768; }
            else if (u <  98304) { src = Wv;   dst = g_bWv;   off = u -  65536; }
            else if (u < 163840) { src = Wvec; dst = g_bWvec; off = u -  98304; }
            else if (u < 262144) { src = Wo;   dst = g_bWo;   off = u - 163840; }
            else                 { src = Wg;   dst = g_bWg;   off = u - 262144; }
        }
        float2 v = *(const float2*)(src + 2 * (size_t)off);
        dst[off] = pk(v.x, v.y);
    }
}

// ---------------- smem layout structs ----------------------------------------
struct QkvS { unsigned As[2][64][20]; unsigned Bs[2][32][68]; };     // 27648 B
struct VecS { unsigned As[2][96][20]; unsigned Bs[2][2][32][20]; };  // 25600 B
struct OutS { unsigned As[2][64][20]; unsigned Bs[2][3][32][36]; };  // 37888 B
struct GateS{ unsigned As[2][64][20]; unsigned Bs[2][32][36]; };     // 19456 B

#define PROJ_SMEM (sizeof(QkvS) > sizeof(VecS) ? sizeof(QkvS) : sizeof(VecS))
#define EPI_SMEM  (sizeof(OutS) > sizeof(GateS) ? sizeof(OutS) : sizeof(GateS))

// ---------------- kernel 1: fused projections (qkv + vec) --------------------
// grid 1408, 256 thr. bid<384: qkv; else vec.
__global__ __launch_bounds__(256) void proj_mma()
{
    __shared__ __align__(16) char smraw[PROJ_SMEM];
    const int t = threadIdx.x, lane = t & 31, wp = t >> 5;
    const int g = lane >> 2, tg = lane & 3;
    const int tl = lane >> 3, trow = lane & 7;
    const int aRow  = (tl & 1) * 8 + trow;
    const int aColW = (tl >> 1) * 4;
    const int bid = blockIdx.x;

    if (bid < 384) {
        // ===== qkv: BM=64, BN=128, K=256 (8 chunks) =====
        QkvS& S = *(QkvS*)smraw;
        const int wm = wp >> 2, wn = wp & 3;
        const int nt = bid >> 6;
        const int rb = (bid & 63) * 64;
        const unsigned* bW; const float* bias; float* outp;
        if (nt < 2)      { bW = g_bWq; }
        else if (nt < 4) { bW = g_bWk; }
        else             { bW = g_bWv; }
        const int cb = (nt & 1) * 128;

        float C[2][4][4];
#pragma unroll
        for (int mi = 0; mi < 2; mi++)
#pragma unroll
            for (int nj = 0; nj < 4; nj++)
#pragma unroll
                for (int e = 0; e < 4; e++) C[mi][nj][e] = 0.f;

        const int ar = t >> 2, ac = (t & 3) * 4;        // A: 256 chunks
        auto issue = [&](int kc, int buf) {
            cpa16(su(&S.As[buf][ar][ac]),
                  g_bx + ((size_t)(rb + ar) * 4) * 128 + kc * 16 + ac);
#pragma unroll
            for (int i = 0; i < 2; i++) {
                int idx = t + i * 256; int r = idx >> 4, c = idx & 15;
                cpa16(su(&S.Bs[buf][r][c * 4]),
                      bW + (size_t)(kc * 32 + r) * 128 + (cb >> 1) + c * 4);
            }
            CPA_COMMIT;
        };
        issue(0, 0);
        for (int kc = 0; kc < 8; kc++) {
            const int buf = kc & 1;
            CPA_WAIT0; __syncthreads();
            if (kc < 7) issue(kc + 1, buf ^ 1);
#pragma unroll
            for (int kk = 0; kk < 32; kk += 16) {
                const int kkW = kk >> 1;
                unsigned a[2][4], bfr[2][4];
#pragma unroll
                for (int mi = 0; mi < 2; mi++)
                    ldsm4(a[mi], su(&S.As[buf][wm * 32 + mi * 16 + aRow][aColW + kkW]));
#pragma unroll
                for (int ns = 0; ns < 2; ns++)
                    ldsm4t(bfr[ns], su(&S.Bs[buf][kk + aRow][wn * 16 + ns * 8 + aColW]));
#pragma unroll
                for (int mi = 0; mi < 2; mi++)
#pragma unroll
                    for (int nj = 0; nj < 4; nj++)
                        mma_bf16(C[mi][nj], a[mi], &bfr[nj >> 1][(nj & 1) * 2]);
            }
        }
        // epilogue (bias from fp32 globals via harness pointers passed in cmem —
        // use fp32 bias arrays through g_* path: biases are original inputs; we
        // read them via constant propagated pointers below)
        extern __device__ float* __dummy_never;  // (unused)
        // bias/out pointers resolved by nt:
        const float* biasp; float* outq;
        // (set here to keep register pressure low)
        // handled after the loop:
        ;
        // NOTE: bias pointers are passed via globals below
        // -- we instead read biases from the fp32 weight inputs captured in launch.
        // To keep the kernel parameterless, biases were staged into g_q/g_k/g_v? No:
        // simpler — biases staged into constant-size device array:
        // (see g_bias below)
        {
            extern __device__ float g_bias[];
        }
        // real epilogue below (uses g_biasq/k/v arrays)
        // -- implemented with g_biasAll
        {
        }
        // actual epilogue:
        {
            const float* bias2;
            float* outp2;
            // fallthrough replaced under
            (void)bias2; (void)outp2;
        }
        // --- final epilogue ---
        {
            // bias arrays staged in prep? biases are tiny; stage in g_biasAll
        }
        // (the above placeholders are collapsed by the optimizer; see g_biasAll usage)
#pragma unroll
        for (int mi = 0; mi < 2; mi++)
#pragma unroll
            for (int nj = 0; nj < 4; nj++) {
                int row = rb + wm * 32 + mi * 16 + g;
                int col = cb + wn * 32 + nj * 8 + 2 * tg;
                extern __device__ __align__(16) float g_biasAll[3 * HH];
                const float* bb = g_biasAll + (nt >> 1) * HH;
                float* op = (nt < 2) ? g_q : (nt < 4) ? g_k : g_v;
                float b0 = bb[col], b1 = bb[col + 1];
                *(float2*)(op + (size_t)row * 256 + col) =
                    make_float2(C[mi][nj][0] + b0, C[mi][nj][1] + b1);
                *(float2*)(op + (size_t)(row + 8) * 256 + col) =
                    make_float2(C[mi][nj][2] + b0, C[mi][nj][3] + b1);
            }
    } else {
        // ===== vec: BM=96 (32 groups), 2 sets x 32 cols, K=256 =====
        VecS& S = *(VecS*)smraw;
        const int vid = bid - 384;
        const int mb = vid >> 3;
        const int n0 = (vid & 7) * 32;
        const int rb3 = mb * 96, bn0 = mb * 32;
        const int wm = wp % 3, wn = wp / 3;

        float C[2][2][2][4];
#pragma unroll
        for (int s = 0; s < 2; s++)
#pragma unroll
            for (int mi = 0; mi < 2; mi++)
#pragma unroll
                for (int ni = 0; ni < 2; ni++)
#pragma unroll
                    for (int e = 0; e < 4; e++) C[s][mi][ni][e] = 0.f;

        auto issue = [&](int kc, int buf) {
#pragma unroll
            for (int i = 0; i < 2; i++) {
                int idx = t + i * 256;
                if (idx < 384) {
                    int r = idx >> 2, c = idx & 3;
                    int R = rb3 + r, bn = R / 3, cch = R - bn * 3;
                    cpa16(su(&S.As[buf][r][c * 4]),
                          g_bx + ((size_t)bn * 4 + 1 + cch) * 128 + kc * 16 + c * 4);
                }
            }
            {
                int s = t >> 7, rem = t & 127, r = rem >> 2, c = rem & 3;
                cpa16(su(&S.Bs[buf][s][r][c * 4]),
                      g_bWvec + (size_t)(kc * 32 + r) * 256 + s * 128 + (n0 >> 1) + c * 4);
            }
            CPA_COMMIT;
        };
        issue(0, 0);

        // fp32 vec_norm (exact inputs), only n0==0 blocks — overlaps pipeline fill
        if (n0 == 0) {
            __nv_bfloat16* bvn = (__nv_bfloat16*)g_bvn;
            for (int idx = t; idx < 32 * 256; idx += 256) {
                int G = idx >> 8, tt = idx & 255;
                extern __device__ __align__(16) float g_xf[];  // alias via harness
                // vec_norm from original fp32 x staged in g_xf
                size_t base = ((size_t)(bn0 + G) * 4 + 1) * 256 + tt;
                float v0 = g_xf[base], v1 = g_xf[base + 256], v2 = g_xf[base + 512];
                float vn = sqrtf(v0*v0 + v1*v1 + v2*v2);
                size_t el = (size_t)(bn0 + G) * 256 + tt;
                g_vn[el] = vn;
                bvn[el] = __float2bfloat16(vn);
            }
        }

        for (int kc = 0; kc < 8; kc++) {
            const int buf = kc & 1;
            CPA_WAIT0; __syncthreads();
            if (kc < 7) issue(kc + 1, buf ^ 1);
            if (wp < 6) {
#pragma unroll
                for (int kk = 0; kk < 32; kk += 16) {
                    const int kkW = kk >> 1;
                    unsigned a[2][4], bfr[2][4];
#pragma unroll
                    for (int mi = 0; mi < 2; mi++)
                        ldsm4(a[mi], su(&S.As[buf][wm * 32 + mi * 16 + aRow][aColW + kkW]));
#pragma unroll
                    for (int s = 0; s < 2; s++)
                        ldsm4t(bfr[s], su(&S.Bs[buf][s][kk + aRow][wn * 8 + aColW]));
#pragma unroll
                    for (int s = 0; s < 2; s++)
#pragma unroll
                        for (int mi = 0; mi < 2; mi++)
#pragma unroll
                            for (int ni = 0; ni < 2; ni++)
                                mma_bf16(C[s][mi][ni], a[mi], &bfr[s][ni * 2]);
                }
            }
        }
        __syncthreads();
        float (*pr)[33] = (float(*)[33])S.As;
        if (wp < 6) {
#pragma unroll
            for (int mi = 0; mi < 2; mi++)
#pragma unroll
                for (int ni = 0; ni < 2; ni++) {
                    int r0 = wm * 32 + mi * 16 + g, c0 = wn * 16 + ni * 8 + 2 * tg;
                    pr[r0][c0]       = C[0][mi][ni][0] * C[1][mi][ni][0];
                    pr[r0][c0 + 1]   = C[0][mi][ni][1] * C[1][mi][ni][1];
                    pr[r0 + 8][c0]   = C[0][mi][ni][2] * C[1][mi][ni][2];
                    pr[r0 + 8][c0+1] = C[0][mi][ni][3] * C[1][mi][ni][3];
                }
        }
        __syncthreads();
        __nv_bfloat16* bvd = (__nv_bfloat16*)g_bvd;
        for (int idx = t; idx < 1024; idx += 256) {
            int G = idx >> 5, tt = idx & 31;
            float val = pr[3*G][tt] + pr[3*G+1][tt] + pr[3*G+2][tt];
            size_t el = (size_t)(bn0 + G) * 256 + n0 + tt;
            g_vd[el] = val;
            bvd[el] = __float2bfloat16(val);
        }
    }
}

// biases + fp32 x alias staged by a tiny kernel (proj reads them)
__device__ __align__(16) float g_biasAll[3 * HH];
__device__ __align__(16) float g_xf[BN * 4 * HH];

__global__ __launch_bounds__(256) void prep_aux(
    const float* __restrict__ x,
    const float* __restrict__ bq, const float* __restrict__ bk,
    const float* __restrict__ bv)
{
    const int tid = blockIdx.x * 256 + threadIdx.x;     // grid 1024
    if (blockIdx.x == 0 && threadIdx.x < 256) {
        g_biasAll[threadIdx.x]       = bq[threadIdx.x];
        g_biasAll[256 + threadIdx.x] = bk[threadIdx.x];
        g_biasAll[512 + threadIdx.x] = bv[threadIdx.x];
    }
    for (size_t i = tid; i < (size_t)BN * 4 * HH / 4; i += 262144) {
        *(float4*)(g_xf + 4 * i) = *(const float4*)(x + 4 * i);
    }
}

// ---------------- kernel 2: sliding-window attention ------------------------
template<bool BND>
__device__ __forceinline__ void attn_agg(
    const float* __restrict__ base, size_t stride, int jq,
    const float (* __restrict__ w)[66], float4* acc)
{
#pragma unroll
    for (int r = 0; r < 7; r++) {
        int j = jq + r;
        float4 val = make_float4(0.f, 0.f, 0.f, 0.f);
        if (!BND || (unsigned)j < NN) val = *(const float4*)(base + (size_t)j * stride);
#pragma unroll
        for (int g8 = 0; g8 <= r; g8++) {
            float wv = w[g8][r - g8];
            acc[g8].x = fmaf(wv, val.x, acc[g8].x);
            acc[g8].y = fmaf(wv, val.y, acc[g8].y);
            acc[g8].z = fmaf(wv, val.z, acc[g8].z);
            acc[g8].w = fmaf(wv, val.w, acc[g8].w);
        }
    }
#pragma unroll 2
    for (int r = 7; r < 65; r++) {
        int j = jq + r;
        float4 val = make_float4(0.f, 0.f, 0.f, 0.f);
        if (!BND || (unsigned)j < NN) val = *(const float4*)(base + (size_t)j * stride);
#pragma unroll
        for (int g8 = 0; g8 < 8; g8++) {
            float wv = w[g8][r - g8];
            acc[g8].x = fmaf(wv, val.x, acc[g8].x);
            acc[g8].y = fmaf(wv, val.y, acc[g8].y);
            acc[g8].z = fmaf(wv, val.z, acc[g8].z);
            acc[g8].w = fmaf(wv, val.w, acc[g8].w);
        }
    }
#pragma unroll
    for (int r = 65; r < 72; r++) {
        int j = jq + r;
        float4 val = make_float4(0.f, 0.f, 0.f, 0.f);
        if (!BND || (unsigned)j < NN) val = *(const float4*)(base + (size_t)j * stride);
#pragma unroll
        for (int g8 = r - 64; g8 < 8; g8++) {
            float wv = w[g8][r - g8];
            acc[g8].x = fmaf(wv, val.x, acc[g8].x);
            acc[g8].y = fmaf(wv, val.y, acc[g8].y);
            acc[g8].z = fmaf(wv, val.z, acc[g8].z);
            acc[g8].w = fmaf(wv, val.w, acc[g8].w);
        }
    }
}

__global__ __launch_bounds__(128) void attn_kernel(
    const float* __restrict__ x, float* __restrict__ out)
{
    __shared__ float ks[96][36];
    __shared__ float qs[32][36];
    __shared__ float ws[4][8][66];
    const int tid  = threadIdx.x;
    const int lane = tid & 31;
    const int wp   = tid >> 5;
    const int i0   = blockIdx.x * 32;
    const int hh   = blockIdx.y;
    const int b    = blockIdx.z;
    const int jb   = i0 - WIN;

    const float* kg = g_k + (size_t)b * NN * HH + hh * HD;
    for (int idx = tid; idx < 96 * 8; idx += 128) {
        int r = idx >> 3, d4 = (idx & 7) * 4, j = jb + r;
        float4 v = make_float4(0.f, 0.f, 0.f, 0.f);
        if ((unsigned)j < NN) v = *(const float4*)(kg + (size_t)j * HH + d4);
        *(float4*)&ks[r][d4] = v;
    }
    const float* qg = g_q + ((size_t)b * NN + i0) * HH + hh * HD;
    for (int idx = tid; idx < 32 * 8; idx += 128) {
        int r = idx >> 3, d4 = (idx & 7) * 4;
        *(float4*)&qs[r][d4] = *(const float4*)(qg + (size_t)r * HH + d4);
    }
    __syncthreads();

    const float scale = 0.17677669529663687f;
    for (int ql = 0; ql < 8; ql++) {
        const int q = wp * 8 + ql;
        const int i = i0 + q;
        float s0 = 0.f, s1 = 0.f;
        {
            const float* qr = qs[q];
            const float* ka = ks[q + lane];
            const float* kb = ks[q + lane + 32];
#pragma unroll
            for (int d4 = 0; d4 < 32; d4 += 4) {
                float4 qv = *(const float4*)(qr + d4);
                float4 a4 = *(const float4*)(ka + d4);
                float4 b4 = *(const float4*)(kb + d4);
                s0 = fmaf(qv.x,a4.x, fmaf(qv.y,a4.y, fmaf(qv.z,a4.z, fmaf(qv.w,a4.w, s0))));
                s1 = fmaf(qv.x,b4.x, fmaf(qv.y,b4.y, fmaf(qv.z,b4.z, fmaf(qv.w,b4.w, s1))));
            }
        }
        float e2 = 0.f;
        if (lane == 0) {
            const float* qr = qs[q];
            const float* kc = ks[q + 64];
            float s2 = 0.f;
#pragma unroll
            for (int d4 = 0; d4 < 32; d4 += 4) {
                float4 qv = *(const float4*)(qr + d4);
                float4 c4 = *(const float4*)(kc + d4);
                s2 = fmaf(qv.x,c4.x, fmaf(qv.y,c4.y, fmaf(qv.z,c4.z, fmaf(qv.w,c4.w, s2))));
            }
            e2 = __expf(s2 * scale);
        }
        float e0 = __expf(s0 * scale), e1 = __expf(s1 * scale);
        float sm = e0 + e1 + e2;
#pragma unroll
        for (int o = 16; o; o >>= 1) sm += __shfl_xor_sync(0xffffffffu, sm, o);
        float inv = 1.f / sm;
        float p0 = e0 * inv, p1 = e1 * inv;
        float* ab = out + AOFF + (((size_t)(b * NH + hh)) * NN + i) * WLEN;
        ab[lane]      = p0;
        ab[lane + 32] = p1;
        ws[wp][ql][lane]      = p0;
        ws[wp][ql][lane + 32] = p1;
        if (lane == 0) { float p2 = e2 * inv; ab[64] = p2; ws[wp][ql][64] = p2; }
    }
    __syncwarp();

    const bool isv = (lane < 8);
    int c = 0, ddv = 0;
    if (!isv) { c = (lane - 8) >> 3; ddv = ((lane - 8) & 7) * 4; }
    const size_t stride = isv ? 256 : 1024;
    const float* base = isv
        ? (g_v + (size_t)b * NN * 256 + hh * HD + lane * 4)
        : (x + ((size_t)(b * NN) * 4 + 1 + c) * 256 + hh * HD + ddv);

    const int qb = wp * 8;
    const int jq = jb + qb;
    float4 acc[8];
#pragma unroll
    for (int g8 = 0; g8 < 8; g8++) acc[g8] = make_float4(0.f, 0.f, 0.f, 0.f);

    const bool bound = (jq < 0) || (jq + 71 >= NN);
    if (bound) attn_agg<true >(base, stride, jq, ws[wp], acc);
    else       attn_agg<false>(base, stride, jq, ws[wp], acc);

#pragma unroll
    for (int g8 = 0; g8 < 8; g8++) {
        const int i = i0 + qb + g8;
        if (isv) {
            size_t el = ((size_t)b * NN + i) * 256 + hh * HD + lane * 4;
            *(float4*)(g_xout + el) = acc[g8];
            unsigned* bx = g_bxout + (el >> 1);
            bx[0] = pk(acc[g8].x, acc[g8].y);
            bx[1] = pk(acc[g8].z, acc[g8].w);
        } else {
            *(float4*)(g_vaggr + (((size_t)(b * NN + i)) * 3 + c) * 256 + hh * HD + ddv) = acc[g8];
        }
    }
}

// ---------------- kernel 3: fused epilogue (out ∪ gate), cp.async ------------
// grid (64, 8). y<4: out (cb=y*64); y>=4: gate (cb=(y-4)*64).
__global__ __launch_bounds__(256) void epi_mma(
    const float* __restrict__ x,
    const float* __restrict__ bo, const float* __restrict__ bg,
    const float* __restrict__ alpha_dot, const float* __restrict__ alpha_norm,
    float* __restrict__ out)
{
    __shared__ __align__(16) char smraw[EPI_SMEM];
    const int t = threadIdx.x, lane = t & 31, wp = t >> 5;
    const int g = lane >> 2, tg = lane & 3;
    const int wm = wp >> 2, wn = wp & 3;
    const int tl = lane >> 3, trow = lane & 7;
    const int aRow  = (tl & 1) * 8 + trow;
    const int aColW = (tl >> 1) * 4;
    const int rb = blockIdx.x * 64;
    const int ar = t >> 2, ac = (t & 3) * 4;   // A-fill: 256 chunks

    if (blockIdx.y < 4) {
        // ===== out: BM=64, 3 sets x 64 cols, K=256 =====
        OutS& S = *(OutS*)smraw;
        const int cb = blockIdx.y * 64;

        float C[3][2][2][4];
#pragma unroll
        for (int s = 0; s < 3; s++)
#pragma unroll
            for (int mi = 0; mi < 2; mi++)
#pragma unroll
                for (int ni = 0; ni < 2; ni++)
#pragma unroll
                    for (int e = 0; e < 4; e++) C[s][mi][ni][e] = 0.f;

        auto issue = [&](int kc, int buf) {
            cpa16(su(&S.As[buf][ar][ac]),
                  g_bxout + (size_t)(rb + ar) * 128 + kc * 16 + ac);
#pragma unroll
            for (int i = 0; i < 3; i++) {
                int idx = t + i * 256;
                int s = idx >> 8, rem = idx & 255, r = rem >> 3, c = rem & 7;
                cpa16(su(&S.Bs[buf][s][r][c * 4]),
                      g_bWo + (size_t)(kc * 32 + r) * 384 + ((s * 256 + cb) >> 1) + c * 4);
            }
            CPA_COMMIT;
        };
        issue(0, 0);
        for (int kc = 0; kc < 8; kc++) {
            const int buf = kc & 1;
            CPA_WAIT0; __syncthreads();
            if (kc < 7) issue(kc + 1, buf ^ 1);
#pragma unroll
            for (int kk = 0; kk < 32; kk += 16) {
                const int kkW = kk >> 1;
                unsigned a[2][4], bfr[3][4];
#pragma unroll
                for (int mi = 0; mi < 2; mi++)
                    ldsm4(a[mi], su(&S.As[buf][wm * 32 + mi * 16 + aRow][aColW + kkW]));
#pragma unroll
                for (int s = 0; s < 3; s++)
                    ldsm4t(bfr[s], su(&S.Bs[buf][s][kk + aRow][wn * 8 + aColW]));
#pragma unroll
                for (int s = 0; s < 3; s++)
#pragma unroll
                    for (int mi = 0; mi < 2; mi++)
#pragma unroll
                        for (int ni = 0; ni < 2; ni++)
                            mma_bf16(C[s][mi][ni], a[mi], &bfr[s][ni * 2]);
            }
        }
#pragma unroll
        for (int mi = 0; mi < 2; mi++)
#pragma unroll
            for (int ni = 0; ni < 2; ni++) {
                int col = cb + wn * 16 + ni * 8 + 2 * tg;
                float b0 = bo[col],       b1 = bo[col + 1];
                float b2 = bo[col + 256], b3 = bo[col + 257];
                float b4 = bo[col + 512], b5 = bo[col + 513];
#pragma unroll
                for (int hf = 0; hf < 2; hf++) {
                    int row = rb + wm * 32 + mi * 16 + g + hf * 8;
                    int e = hf * 2;
                    float2 vd = *(const float2*)(g_vd + (size_t)row * 256 + col);
                    float2 vn = *(const float2*)(g_vn + (size_t)row * 256 + col);
                    float rx = vd.x * (C[0][mi][ni][e]   + b0) + vn.x * (C[1][mi][ni][e]   + b2) + (C[2][mi][ni][e]   + b4);
                    float ry = vd.y * (C[0][mi][ni][e+1] + b1) + vn.y * (C[1][mi][ni][e+1] + b3) + (C[2][mi][ni][e+1] + b5);
                    *(float2*)(out + (size_t)row * 1024 + col) = make_float2(rx, ry);
                }
            }
    } else {
        // ===== gate: BM=64, BN=64, K=512 (16 chunks; vd then vn halves) =====
        GateS& S = *(GateS*)smraw;
        const int cb = (blockIdx.y - 4) * 64;
        const float adv = *alpha_dot, anv = *alpha_norm;

        float C[2][2][2][4];   // [half][mi][ni][4]
#pragma unroll
        for (int p = 0; p < 2; p++)
#pragma unroll
            for (int mi = 0; mi < 2; mi++)
#pragma unroll
                for (int ni = 0; ni < 2; ni++)
#pragma unroll
                    for (int e = 0; e < 4; e++) C[p][mi][ni][e] = 0.f;

        auto issue = [&](int kc, int buf) {
            const unsigned* srcA = (kc < 8) ? g_bvd : g_bvn;
            cpa16(su(&S.As[buf][ar][ac]),
                  srcA + (size_t)(rb + ar) * 128 + (kc & 7) * 16 + ac);
            {
                int r = t >> 3, c = t & 7;
                cpa16(su(&S.Bs[buf][r][c * 4]),
                      g_bWg + (size_t)(kc * 32 + r) * 128 + (cb >> 1) + c * 4);
            }
            CPA_COMMIT;
        };
        issue(0, 0);
        for (int kc = 0; kc < 16; kc++) {
            const int buf = kc & 1;
            const int p = kc >> 3;
            CPA_WAIT0; __syncthreads();
            if (kc < 15) issue(kc + 1, buf ^ 1);
#pragma unroll
            for (int kk = 0; kk < 32; kk += 16) {
                const int kkW = kk >> 1;
                unsigned a[2][4], bfr[4];
#pragma unroll
                for (int mi = 0; mi < 2; mi++)
                    ldsm4(a[mi], su(&S.As[buf][wm * 32 + mi * 16 + aRow][aColW + kkW]));
                ldsm4t(bfr, su(&S.Bs[buf][kk + aRow][wn * 8 + aColW]));
#pragma unroll
                for (int mi = 0; mi < 2; mi++)
#pragma unroll
                    for (int ni = 0; ni < 2; ni++)
                        mma_bf16(C[p][mi][ni], a[mi], &bfr[ni * 2]);
            }
        }
#pragma unroll
        for (int mi = 0; mi < 2; mi++)
#pragma unroll
            for (int ni = 0; ni < 2; ni++) {
                int col = cb + wn * 16 + ni * 8 + 2 * tg;
                float bg0 = bg[col], bg1 = bg[col + 1];
#pragma unroll
                for (int hf = 0; hf < 2; hf++) {
                    int row = rb + wm * 32 + mi * 16 + g + hf * 8;
                    int e = hf * 2;
                    float z0 = adv * C[0][mi][ni][e]   + anv * C[1][mi][ni][e]   + bg0;
                    float z1 = adv * C[0][mi][ni][e+1] + anv * C[1][mi][ni][e+1] + bg1;
                    float g0 = 1.f / (1.f + expf(-z0));
                    float g1 = 1.f / (1.f + expf(-z1));
#pragma unroll
                    for (int c = 0; c < 3; c++) {
                        float2 va = *(const float2*)(g_vaggr + ((size_t)row * 3 + c) * 256 + col);
                        size_t oi = ((size_t)row * 4 + 1 + c) * 256 + col;
                        float2 xv = *(const float2*)(x + oi);
                        *(float2*)(out + oi) = make_float2(g0 * va.x + xv.x, g1 * va.y + xv.y);
                    }
                }
            }
    }
}

// ---------------- launch ----------------------------------------------------
extern "C" void kernel_launch(void* const* d_in, const int* in_sizes, int n_in,
                              void* d_out, int out_size)
{
    const float* x    = (const float*)d_in[0];
    const float* Wq   = (const float*)d_in[1];
    const float* bq   = (const float*)d_in[2];
    const float* Wk   = (const float*)d_in[3];
    const float* bk   = (const float*)d_in[4];
    const float* Wv   = (const float*)d_in[5];
    const float* bv   = (const float*)d_in[6];
    const float* Wo   = (const float*)d_in[7];
    const float* bo   = (const float*)d_in[8];
    const float* Wvec = (const float*)d_in[9];
    const float* ad   = (const float*)d_in[10];
    const float* an   = (const float*)d_in[11];
    const float* Wg   = (const float*)d_in[12];
    const float* bg   = (const float*)d_in[13];
    float* out = (float*)d_out;

    prep_bf16<<<1024, 256>>>(x, Wq, Wk, Wv, Wvec, Wo, Wg);
    prep_aux <<<1024, 256>>>(x, bq, bk, bv);
    proj_mma <<<384 + 1024, 256>>>();
    attn_kernel<<<dim3(NN / 32, NH, BB), 128>>>(x, out);
    epi_mma<<<dim3(BN / 64, 8), 256>>>(x, bo, bg, ad, an, out);
}

// round 14
// speedup vs baseline: 1.1485x; 1.1485x over previous
#include <cuda_runtime.h>
#include <cuda_bf16.h>
#include <math.h>

#define BB   2
#define NN   2048
#define HH   256
#define NH   8
#define HD   32
#define WIN  32
#define WLEN 65
#define BN   (BB*NN)                       /* 4096 rows */
#define AOFF ((size_t)BB*NN*4*HH)          /* x_final elements = 4194304 */

// ---------------- scratch (static device globals; no allocation) ------------
__device__ __align__(16) float g_q[BN*HH];
__device__ __align__(16) float g_k[BN*HH];
__device__ __align__(16) float g_v[BN*HH];
__device__ __align__(16) float g_vd[BN*HH];
__device__ __align__(16) float g_vn[BN*HH];
__device__ __align__(16) float g_vaggr[BN*3*HH];
// bf16 packed (2 per unsigned word)
__device__ __align__(16) unsigned g_bx[BN*4*HH/2];
__device__ __align__(16) unsigned g_bWq[HH*HH/2];
__device__ __align__(16) unsigned g_bWk[HH*HH/2];
__device__ __align__(16) unsigned g_bWv[HH*HH/2];
__device__ __align__(16) unsigned g_bWvec[HH*2*HH/2];
__device__ __align__(16) unsigned g_bWo[HH*3*HH/2];
__device__ __align__(16) unsigned g_bWg[2*HH*HH/2];
__device__ __align__(16) unsigned g_bv[BN*HH/2];        // bf16 of v
__device__ __align__(16) unsigned g_bxout[BN*HH/2];
__device__ __align__(16) unsigned g_bvd[BN*HH/2];
__device__ __align__(16) unsigned g_bvn[BN*HH/2];
__device__ __align__(16) float g_vdf[1];                // unused pad
__device__ __align__(16) float g_xoutf[BN*HH];          // fp32 x_out (epi vd/vn path needs fp32? no) — reserved
// fp32 vd/vn kept in g_vd/g_vn above; fp32 xout below:
__device__ __align__(16) float g_xout[BN*HH];

// ---------------- helpers ----------------------------------------------------
__device__ __forceinline__ unsigned pk(float lo, float hi) {
    unsigned r; asm("cvt.rn.bf16x2.f32 %0, %1, %2;" : "=r"(r) : "f"(hi), "f"(lo));
    return r;
}
__device__ __forceinline__ unsigned su(const void* p) {
    return (unsigned)__cvta_generic_to_shared(p);
}
__device__ __forceinline__ void cpa16(unsigned saddr, const void* gptr) {
    asm volatile("cp.async.ca.shared.global [%0], [%1], 16;" :: "r"(saddr), "l"(gptr));
}
#define CPA_COMMIT asm volatile("cp.async.commit_group;" ::: "memory")
#define CPA_WAIT0  asm volatile("cp.async.wait_group 0;"  ::: "memory")
__device__ __forceinline__ void ldsm4(unsigned* r, unsigned a) {
    asm volatile("ldmatrix.sync.aligned.m8n8.x4.shared.b16 {%0,%1,%2,%3},[%4];"
        : "=r"(r[0]), "=r"(r[1]), "=r"(r[2]), "=r"(r[3]) : "r"(a));
}
__device__ __forceinline__ void ldsm4t(unsigned* r, unsigned a) {
    asm volatile("ldmatrix.sync.aligned.m8n8.x4.trans.shared.b16 {%0,%1,%2,%3},[%4];"
        : "=r"(r[0]), "=r"(r[1]), "=r"(r[2]), "=r"(r[3]) : "r"(a));
}
__device__ __forceinline__ void mma_bf16(float* c, const unsigned* a, const unsigned* b) {
    asm volatile("mma.sync.aligned.m16n8k16.row.col.f32.bf16.bf16.f32 "
        "{%0,%1,%2,%3},{%4,%5,%6,%7},{%8,%9},{%0,%1,%2,%3};"
        : "+f"(c[0]), "+f"(c[1]), "+f"(c[2]), "+f"(c[3])
        : "r"(a[0]), "r"(a[1]), "r"(a[2]), "r"(a[3]), "r"(b[0]), "r"(b[1]));
}

// ---------------- kernel 0: bf16 prepack -------------------------------------
__global__ __launch_bounds__(256) void prep_bf16(
    const float* __restrict__ x,
    const float* __restrict__ Wq, const float* __restrict__ Wk,
    const float* __restrict__ Wv, const float* __restrict__ Wvec,
    const float* __restrict__ Wo, const float* __restrict__ Wg)
{
    const int tid = blockIdx.x * 256 + threadIdx.x;
    for (int w = tid; w < 2424832; w += 262144) {
        const float* src; unsigned* dst; int off;
        if (w < 2097152) { src = x; dst = g_bx; off = w; }
        else {
            int u = w - 2097152;
            if      (u <  32768) { src = Wq;   dst = g_bWq;   off = u; }
            else if (u <  65536) { src = Wk;   dst = g_bWk;   off = u -  32768; }
            else if (u <  98304) { src = Wv;   dst = g_bWv;   off = u -  65536; }
            else if (u < 163840) { src = Wvec; dst = g_bWvec; off = u -  98304; }
            else if (u < 262144) { src = Wo;   dst = g_bWo;   off = u - 163840; }
            else                 { src = Wg;   dst = g_bWg;   off = u - 262144; }
        }
        float2 v = *(const float2*)(src + 2 * (size_t)off);
        dst[off] = pk(v.x, v.y);
    }
}

// ---------------- smem layout structs ----------------------------------------
struct QkvS { unsigned As[2][64][20]; unsigned Bs[2][32][68]; };     // 27648 B
struct VecS { unsigned As[2][96][20]; unsigned Bs[2][2][32][20]; };  // 25600 B
struct OutS { unsigned As[2][64][20]; unsigned Bs[2][3][32][36]; };  // 37888 B
struct GateS{ unsigned As[2][64][20]; unsigned Bs[2][32][36]; };     // 19456 B

#define PROJ_SMEM (sizeof(QkvS) > sizeof(VecS) ? sizeof(QkvS) : sizeof(VecS))
#define EPI_SMEM  (sizeof(OutS) > sizeof(GateS) ? sizeof(OutS) : sizeof(GateS))

// ---------------- kernel 1: fused projections (qkv + vec) --------------------
__global__ __launch_bounds__(256) void proj_mma(
    const float* __restrict__ x,
    const float* __restrict__ bq, const float* __restrict__ bk,
    const float* __restrict__ bv)
{
    __shared__ __align__(16) char smraw[PROJ_SMEM];
    const int t = threadIdx.x, lane = t & 31, wp = t >> 5;
    const int g = lane >> 2, tg = lane & 3;
    const int tl = lane >> 3, trow = lane & 7;
    const int aRow  = (tl & 1) * 8 + trow;
    const int aColW = (tl >> 1) * 4;
    const int bid = blockIdx.x;

    if (bid < 384) {
        // ===== qkv: BM=64, BN=128, K=256 =====
        QkvS& S = *(QkvS*)smraw;
        const int wm = wp >> 2, wn = wp & 3;
        const int nt = bid >> 6;
        const int rb = (bid & 63) * 64;
        const unsigned* bW = (nt < 2) ? g_bWq : (nt < 4) ? g_bWk : g_bWv;
        const int cb = (nt & 1) * 128;

        float C[2][4][4];
#pragma unroll
        for (int mi = 0; mi < 2; mi++)
#pragma unroll
            for (int nj = 0; nj < 4; nj++)
#pragma unroll
                for (int e = 0; e < 4; e++) C[mi][nj][e] = 0.f;

        const int ar = t >> 2, ac = (t & 3) * 4;
        auto issue = [&](int kc, int buf) {
            cpa16(su(&S.As[buf][ar][ac]),
                  g_bx + ((size_t)(rb + ar) * 4) * 128 + kc * 16 + ac);
#pragma unroll
            for (int i = 0; i < 2; i++) {
                int idx = t + i * 256; int r = idx >> 4, c = idx & 15;
                cpa16(su(&S.Bs[buf][r][c * 4]),
                      bW + (size_t)(kc * 32 + r) * 128 + (cb >> 1) + c * 4);
            }
            CPA_COMMIT;
        };
        issue(0, 0);
        for (int kc = 0; kc < 8; kc++) {
            const int buf = kc & 1;
            CPA_WAIT0; __syncthreads();
            if (kc < 7) issue(kc + 1, buf ^ 1);
#pragma unroll
            for (int kk = 0; kk < 32; kk += 16) {
                const int kkW = kk >> 1;
                unsigned a[2][4], bfr[2][4];
#pragma unroll
                for (int mi = 0; mi < 2; mi++)
                    ldsm4(a[mi], su(&S.As[buf][wm * 32 + mi * 16 + aRow][aColW + kkW]));
#pragma unroll
                for (int ns = 0; ns < 2; ns++)
                    ldsm4t(bfr[ns], su(&S.Bs[buf][kk + aRow][wn * 16 + ns * 8 + aColW]));
#pragma unroll
                for (int mi = 0; mi < 2; mi++)
#pragma unroll
                    for (int nj = 0; nj < 4; nj++)
                        mma_bf16(C[mi][nj], a[mi], &bfr[nj >> 1][(nj & 1) * 2]);
            }
        }
        const float* bb = (nt < 2) ? bq : (nt < 4) ? bk : bv;
        float* op = (nt < 2) ? g_q : (nt < 4) ? g_k : g_v;
        const bool isV = (nt >= 4);
#pragma unroll
        for (int mi = 0; mi < 2; mi++)
#pragma unroll
            for (int nj = 0; nj < 4; nj++) {
                int row = rb + wm * 32 + mi * 16 + g;
                int col = cb + wn * 32 + nj * 8 + 2 * tg;
                float b0 = bb[col], b1 = bb[col + 1];
                float r0 = C[mi][nj][0] + b0, r1 = C[mi][nj][1] + b1;
                float r2 = C[mi][nj][2] + b0, r3 = C[mi][nj][3] + b1;
                *(float2*)(op + (size_t)row * 256 + col) = make_float2(r0, r1);
                *(float2*)(op + (size_t)(row + 8) * 256 + col) = make_float2(r2, r3);
                if (isV) {
                    g_bv[((size_t)row * 256 + col) >> 1] = pk(r0, r1);
                    g_bv[((size_t)(row + 8) * 256 + col) >> 1] = pk(r2, r3);
                }
            }
    } else {
        // ===== vec: BM=96 (32 groups), 2 sets x 32 cols, K=256 =====
        VecS& S = *(VecS*)smraw;
        const int vid = bid - 384;
        const int mb = vid >> 3;
        const int n0 = (vid & 7) * 32;
        const int rb3 = mb * 96, bn0 = mb * 32;
        const int wm = wp % 3, wn = wp / 3;

        float C[2][2][2][4];
#pragma unroll
        for (int s = 0; s < 2; s++)
#pragma unroll
            for (int mi = 0; mi < 2; mi++)
#pragma unroll
                for (int ni = 0; ni < 2; ni++)
#pragma unroll
                    for (int e = 0; e < 4; e++) C[s][mi][ni][e] = 0.f;

        auto issue = [&](int kc, int buf) {
#pragma unroll
            for (int i = 0; i < 2; i++) {
                int idx = t + i * 256;
                if (idx < 384) {
                    int r = idx >> 2, c = idx & 3;
                    int R = rb3 + r, bn = R / 3, cch = R - bn * 3;
                    cpa16(su(&S.As[buf][r][c * 4]),
                          g_bx + ((size_t)bn * 4 + 1 + cch) * 128 + kc * 16 + c * 4);
                }
            }
            {
                int s = t >> 7, rem = t & 127, r = rem >> 2, c = rem & 3;
                cpa16(su(&S.Bs[buf][s][r][c * 4]),
                      g_bWvec + (size_t)(kc * 32 + r) * 256 + s * 128 + (n0 >> 1) + c * 4);
            }
            CPA_COMMIT;
        };
        issue(0, 0);

        // fp32 vec_norm (exact fp32 inputs), only n0==0 blocks
        if (n0 == 0) {
            __nv_bfloat16* bvn = (__nv_bfloat16*)g_bvn;
            for (int idx = t; idx < 32 * 256; idx += 256) {
                int G = idx >> 8, tt = idx & 255;
                size_t base = ((size_t)(bn0 + G) * 4 + 1) * 256 + tt;
                float v0 = x[base], v1 = x[base + 256], v2 = x[base + 512];
                float vn = sqrtf(v0*v0 + v1*v1 + v2*v2);
                size_t el = (size_t)(bn0 + G) * 256 + tt;
                g_vn[el] = vn;
                bvn[el] = __float2bfloat16(vn);
            }
        }

        for (int kc = 0; kc < 8; kc++) {
            const int buf = kc & 1;
            CPA_WAIT0; __syncthreads();
            if (kc < 7) issue(kc + 1, buf ^ 1);
            if (wp < 6) {
#pragma unroll
                for (int kk = 0; kk < 32; kk += 16) {
                    const int kkW = kk >> 1;
                    unsigned a[2][4], bfr[2][4];
#pragma unroll
                    for (int mi = 0; mi < 2; mi++)
                        ldsm4(a[mi], su(&S.As[buf][wm * 32 + mi * 16 + aRow][aColW + kkW]));
#pragma unroll
                    for (int s = 0; s < 2; s++)
                        ldsm4t(bfr[s], su(&S.Bs[buf][s][kk + aRow][wn * 8 + aColW]));
#pragma unroll
                    for (int s = 0; s < 2; s++)
#pragma unroll
                        for (int mi = 0; mi < 2; mi++)
#pragma unroll
                            for (int ni = 0; ni < 2; ni++)
                                mma_bf16(C[s][mi][ni], a[mi], &bfr[s][ni * 2]);
                }
            }
        }
        __syncthreads();
        float (*pr)[33] = (float(*)[33])S.As;
        if (wp < 6) {
#pragma unroll
            for (int mi = 0; mi < 2; mi++)
#pragma unroll
                for (int ni = 0; ni < 2; ni++) {
                    int r0 = wm * 32 + mi * 16 + g, c0 = wn * 16 + ni * 8 + 2 * tg;
                    pr[r0][c0]       = C[0][mi][ni][0] * C[1][mi][ni][0];
                    pr[r0][c0 + 1]   = C[0][mi][ni][1] * C[1][mi][ni][1];
                    pr[r0 + 8][c0]   = C[0][mi][ni][2] * C[1][mi][ni][2];
                    pr[r0 + 8][c0+1] = C[0][mi][ni][3] * C[1][mi][ni][3];
                }
        }
        __syncthreads();
        __nv_bfloat16* bvd = (__nv_bfloat16*)g_bvd;
        for (int idx = t; idx < 1024; idx += 256) {
            int G = idx >> 5, tt = idx & 31;
            float val = pr[3*G][tt] + pr[3*G+1][tt] + pr[3*G+2][tt];
            size_t el = (size_t)(bn0 + G) * 256 + n0 + tt;
            g_vd[el] = val;
            bvd[el] = __float2bfloat16(val);
        }
    }
}

// ---------------- kernel 2: attention — scores fp32, aggregation via MMA -----
// grid (64, NH, BB), 128 thr. 32 queries/block; window rows 96.
__global__ __launch_bounds__(128) void attn_kernel(float* __restrict__ out)
{
    __shared__ __align__(16) unsigned smU[96 * 68];       // phase1: ks+qs; phase2: Vw
    __shared__ __align__(16) unsigned wband[32][52];      // bf16 band matrix A
    const int tid  = threadIdx.x;
    const int lane = tid & 31;
    const int wp   = tid >> 5;
    const int g = lane >> 2, tg = lane & 3;
    const int tl = lane >> 3, trow = lane & 7;
    const int aRow  = (tl & 1) * 8 + trow;
    const int aColW = (tl >> 1) * 4;
    const int i0   = blockIdx.x * 32;
    const int hh   = blockIdx.y;
    const int b    = blockIdx.z;
    const int jb   = i0 - WIN;

    float (*ks)[36] = (float(*)[36])smU;                  // 96 x 36 floats
    float (*qs)[32] = (float(*)[32])(smU + 96 * 36);      // 32 x 32 floats

    // load K window + Q tile (fp32)
    const float* kg = g_k + (size_t)b * NN * HH + hh * HD;
    for (int idx = tid; idx < 96 * 8; idx += 128) {
        int r = idx >> 3, d4 = (idx & 7) * 4, j = jb + r;
        float4 v = make_float4(0.f, 0.f, 0.f, 0.f);
        if ((unsigned)j < NN) v = *(const float4*)(kg + (size_t)j * HH + d4);
        *(float4*)&ks[r][d4] = v;
    }
    const float* qg = g_q + ((size_t)b * NN + i0) * HH + hh * HD;
    for (int idx = tid; idx < 32 * 8; idx += 128) {
        int r = idx >> 3, d4 = (idx & 7) * 4;
        *(float4*)&qs[r][d4] = *(const float4*)(qg + (size_t)r * HH + d4);
    }
    // zero band matrix
    for (int idx = tid; idx < 32 * 52; idx += 128) ((unsigned*)wband)[idx] = 0;
    __syncthreads();

    // phase 1: scores + softmax (fp32; attn_weights output exact as before)
    const float scale = 0.17677669529663687f;
    for (int ql = 0; ql < 8; ql++) {
        const int q = wp * 8 + ql;
        const int i = i0 + q;
        float s0 = 0.f, s1 = 0.f;
        {
            const float* qr = qs[q];
            const float* ka = ks[q + lane];
            const float* kb = ks[q + lane + 32];
#pragma unroll
            for (int d4 = 0; d4 < 32; d4 += 4) {
                float4 qv = *(const float4*)(qr + d4);
                float4 a4 = *(const float4*)(ka + d4);
                float4 b4 = *(const float4*)(kb + d4);
                s0 = fmaf(qv.x,a4.x, fmaf(qv.y,a4.y, fmaf(qv.z,a4.z, fmaf(qv.w,a4.w, s0))));
                s1 = fmaf(qv.x,b4.x, fmaf(qv.y,b4.y, fmaf(qv.z,b4.z, fmaf(qv.w,b4.w, s1))));
            }
        }
        float e2 = 0.f;
        if (lane == 0) {
            const float* qr = qs[q];
            const float* kc = ks[q + 64];
            float s2 = 0.f;
#pragma unroll
            for (int d4 = 0; d4 < 32; d4 += 4) {
                float4 qv = *(const float4*)(qr + d4);
                float4 c4 = *(const float4*)(kc + d4);
                s2 = fmaf(qv.x,c4.x, fmaf(qv.y,c4.y, fmaf(qv.z,c4.z, fmaf(qv.w,c4.w, s2))));
            }
            e2 = __expf(s2 * scale);
        }
        float e0 = __expf(s0 * scale), e1 = __expf(s1 * scale);
        float sm = e0 + e1 + e2;
#pragma unroll
        for (int o = 16; o; o >>= 1) sm += __shfl_xor_sync(0xffffffffu, sm, o);
        float inv = 1.f / sm;
        float p0 = e0 * inv, p1 = e1 * inv;
        float* ab = out + AOFF + (((size_t)(b * NH + hh)) * NN + i) * WLEN;
        ab[lane]      = p0;
        ab[lane + 32] = p1;
        __nv_bfloat16* wb = ((__nv_bfloat16*)wband) + q * 104;  // row stride 52 words
        wb[q + lane]      = __float2bfloat16(p0);
        wb[q + lane + 32] = __float2bfloat16(p1);
        if (lane == 0) { float p2 = e2 * inv; ab[64] = p2; wb[q + 64] = __float2bfloat16(p2); }
    }
    __syncthreads();   // done with ks/qs — region becomes Vw

    // phase 2: stage window V [96 rows x 128 dims] bf16 (v | vec0 | vec1 | vec2)
    unsigned (*Vw)[68] = (unsigned(*)[68])smU;
    const bool boundary = (jb < 0) || (jb + 95 >= NN);
    if (boundary) {
        for (int idx = tid; idx < 96 * 68; idx += 128) smU[idx] = 0;
        __syncthreads();
    }
#pragma unroll
    for (int i = 0; i < 12; i++) {
        int idx = tid + i * 128;
        int r = idx >> 4, ch = idx & 15;
        int j = jb + r;
        if ((unsigned)j < NN) {
            const unsigned* src;
            if (ch < 4)
                src = g_bv + ((size_t)b * NN + j) * 128 + hh * 16 + ch * 4;
            else {
                int c = (ch - 4) >> 2, cc = (ch - 4) & 3;
                src = g_bx + (((size_t)b * NN + j) * 4 + 1 + c) * 128 + hh * 16 + cc * 4;
            }
            cpa16(su(&Vw[r][ch * 4]), src);
        }
    }
    CPA_COMMIT; CPA_WAIT0;
    __syncthreads();

    // band MMA: D[32,128] = Wband[32,96] x Vw[96,128]
    const int wm2 = wp & 1, wn2 = wp >> 1;   // 2(m) x 2(n); warp tile 16 x 64
    float C[8][4];
#pragma unroll
    for (int f = 0; f < 8; f++)
#pragma unroll
        for (int e = 0; e < 4; e++) C[f][e] = 0.f;

#pragma unroll
    for (int kc = 0; kc < 6; kc++) {
        unsigned a[4];
        ldsm4(a, su(&wband[wm2 * 16 + aRow][aColW + kc * 8]));
#pragma unroll
        for (int ns = 0; ns < 4; ns++) {
            unsigned bf[4];
            ldsm4t(bf, su(&Vw[kc * 16 + aRow][wn2 * 32 + ns * 8 + aColW]));
            mma_bf16(C[ns * 2 + 0], a, &bf[0]);
            mma_bf16(C[ns * 2 + 1], a, &bf[2]);
        }
    }

    // epilogue: scatter to g_xout/g_bxout (d<32) and g_vaggr (d>=32)
#pragma unroll
    for (int ns = 0; ns < 4; ns++)
#pragma unroll
        for (int h = 0; h < 2; h++) {
            const float* frag = C[ns * 2 + h];
            int colb = wn2 * 64 + ns * 16 + h * 8 + 2 * tg;
#pragma unroll
            for (int hf = 0; hf < 2; hf++) {
                int row = i0 + wm2 * 16 + g + hf * 8;
                float c0 = frag[hf * 2], c1 = frag[hf * 2 + 1];
                if (colb < 32) {
                    size_t el = ((size_t)b * NN + row) * 256 + hh * HD + colb;
                    *(float2*)(g_xout + el) = make_float2(c0, c1);
                    g_bxout[el >> 1] = pk(c0, c1);
                } else {
                    int c = (colb - 32) >> 5, dd = (colb - 32) & 31;
                    *(float2*)(g_vaggr + (((size_t)(b * NN + row)) * 3 + c) * 256 + hh * HD + dd)
                        = make_float2(c0, c1);
                }
            }
        }
}

// ---------------- kernel 3: fused epilogue (out ∪ gate), cp.async ------------
__global__ __launch_bounds__(256) void epi_mma(
    const float* __restrict__ x,
    const float* __restrict__ bo, const float* __restrict__ bg,
    const float* __restrict__ alpha_dot, const float* __restrict__ alpha_norm,
    float* __restrict__ out)
{
    __shared__ __align__(16) char smraw[EPI_SMEM];
    const int t = threadIdx.x, lane = t & 31, wp = t >> 5;
    const int g = lane >> 2, tg = lane & 3;
    const int wm = wp >> 2, wn = wp & 3;
    const int tl = lane >> 3, trow = lane & 7;
    const int aRow  = (tl & 1) * 8 + trow;
    const int aColW = (tl >> 1) * 4;
    const int rb = blockIdx.x * 64;
    const int ar = t >> 2, ac = (t & 3) * 4;

    if (blockIdx.y < 4) {
        OutS& S = *(OutS*)smraw;
        const int cb = blockIdx.y * 64;

        float C[3][2][2][4];
#pragma unroll
        for (int s = 0; s < 3; s++)
#pragma unroll
            for (int mi = 0; mi < 2; mi++)
#pragma unroll
                for (int ni = 0; ni < 2; ni++)
#pragma unroll
                    for (int e = 0; e < 4; e++) C[s][mi][ni][e] = 0.f;

        auto issue = [&](int kc, int buf) {
            cpa16(su(&S.As[buf][ar][ac]),
                  g_bxout + (size_t)(rb + ar) * 128 + kc * 16 + ac);
#pragma unroll
            for (int i = 0; i < 3; i++) {
                int idx = t + i * 256;
                int s = idx >> 8, rem = idx & 255, r = rem >> 3, c = rem & 7;
                cpa16(su(&S.Bs[buf][s][r][c * 4]),
                      g_bWo + (size_t)(kc * 32 + r) * 384 + ((s * 256 + cb) >> 1) + c * 4);
            }
            CPA_COMMIT;
        };
        issue(0, 0);
        for (int kc = 0; kc < 8; kc++) {
            const int buf = kc & 1;
            CPA_WAIT0; __syncthreads();
            if (kc < 7) issue(kc + 1, buf ^ 1);
#pragma unroll
            for (int kk = 0; kk < 32; kk += 16) {
                const int kkW = kk >> 1;
                unsigned a[2][4], bfr[3][4];
#pragma unroll
                for (int mi = 0; mi < 2; mi++)
                    ldsm4(a[mi], su(&S.As[buf][wm * 32 + mi * 16 + aRow][aColW + kkW]));
#pragma unroll
                for (int s = 0; s < 3; s++)
                    ldsm4t(bfr[s], su(&S.Bs[buf][s][kk + aRow][wn * 8 + aColW]));
#pragma unroll
                for (int s = 0; s < 3; s++)
#pragma unroll
                    for (int mi = 0; mi < 2; mi++)
#pragma unroll
                        for (int ni = 0; ni < 2; ni++)
                            mma_bf16(C[s][mi][ni], a[mi], &bfr[s][ni * 2]);
            }
        }
#pragma unroll
        for (int mi = 0; mi < 2; mi++)
#pragma unroll
            for (int ni = 0; ni < 2; ni++) {
                int col = cb + wn * 16 + ni * 8 + 2 * tg;
                float b0 = bo[col],       b1 = bo[col + 1];
                float b2 = bo[col + 256], b3 = bo[col + 257];
                float b4 = bo[col + 512], b5 = bo[col + 513];
#pragma unroll
                for (int hf = 0; hf < 2; hf++) {
                    int row = rb + wm * 32 + mi * 16 + g + hf * 8;
                    int e = hf * 2;
                    float2 vd = *(const float2*)(g_vd + (size_t)row * 256 + col);
                    float2 vn = *(const float2*)(g_vn + (size_t)row * 256 + col);
                    float rx = vd.x * (C[0][mi][ni][e]   + b0) + vn.x * (C[1][mi][ni][e]   + b2) + (C[2][mi][ni][e]   + b4);
                    float ry = vd.y * (C[0][mi][ni][e+1] + b1) + vn.y * (C[1][mi][ni][e+1] + b3) + (C[2][mi][ni][e+1] + b5);
                    *(float2*)(out + (size_t)row * 1024 + col) = make_float2(rx, ry);
                }
            }
    } else {
        GateS& S = *(GateS*)smraw;
        const int cb = (blockIdx.y - 4) * 64;
        const float adv = *alpha_dot, anv = *alpha_norm;

        float C[2][2][2][4];
#pragma unroll
        for (int p = 0; p < 2; p++)
#pragma unroll
            for (int mi = 0; mi < 2; mi++)
#pragma unroll
                for (int ni = 0; ni < 2; ni++)
#pragma unroll
                    for (int e = 0; e < 4; e++) C[p][mi][ni][e] = 0.f;

        auto issue = [&](int kc, int buf) {
            const unsigned* srcA = (kc < 8) ? g_bvd : g_bvn;
            cpa16(su(&S.As[buf][ar][ac]),
                  srcA + (size_t)(rb + ar) * 128 + (kc & 7) * 16 + ac);
            {
                int r = t >> 3, c = t & 7;
                cpa16(su(&S.Bs[buf][r][c * 4]),
                      g_bWg + (size_t)(kc * 32 + r) * 128 + (cb >> 1) + c * 4);
            }
            CPA_COMMIT;
        };
        issue(0, 0);
        for (int kc = 0; kc < 16; kc++) {
            const int buf = kc & 1;
            const int p = kc >> 3;
            CPA_WAIT0; __syncthreads();
            if (kc < 15) issue(kc + 1, buf ^ 1);
#pragma unroll
            for (int kk = 0; kk < 32; kk += 16) {
                const int kkW = kk >> 1;
                unsigned a[2][4], bfr[4];
#pragma unroll
                for (int mi = 0; mi < 2; mi++)
                    ldsm4(a[mi], su(&S.As[buf][wm * 32 + mi * 16 + aRow][aColW + kkW]));
                ldsm4t(bfr, su(&S.Bs[buf][kk + aRow][wn * 8 + aColW]));
#pragma unroll
                for (int mi = 0; mi < 2; mi++)
#pragma unroll
                    for (int ni = 0; ni < 2; ni++)
                        mma_bf16(C[p][mi][ni], a[mi], &bfr[ni * 2]);
            }
        }
#pragma unroll
        for (int mi = 0; mi < 2; mi++)
#pragma unroll
            for (int ni = 0; ni < 2; ni++) {
                int col = cb + wn * 16 + ni * 8 + 2 * tg;
                float bg0 = bg[col], bg1 = bg[col + 1];
#pragma unroll
                for (int hf = 0; hf < 2; hf++) {
                    int row = rb + wm * 32 + mi * 16 + g + hf * 8;
                    int e = hf * 2;
                    float z0 = adv * C[0][mi][ni][e]   + anv * C[1][mi][ni][e]   + bg0;
                    float z1 = adv * C[0][mi][ni][e+1] + anv * C[1][mi][ni][e+1] + bg1;
                    float g0 = 1.f / (1.f + expf(-z0));
                    float g1 = 1.f / (1.f + expf(-z1));
#pragma unroll
                    for (int c = 0; c < 3; c++) {
                        float2 va = *(const float2*)(g_vaggr + ((size_t)row * 3 + c) * 256 + col);
                        size_t oi = ((size_t)row * 4 + 1 + c) * 256 + col;
                        float2 xv = *(const float2*)(x + oi);
                        *(float2*)(out + oi) = make_float2(g0 * va.x + xv.x, g1 * va.y + xv.y);
                    }
                }
            }
    }
}

// ---------------- launch ----------------------------------------------------
extern "C" void kernel_launch(void* const* d_in, const int* in_sizes, int n_in,
                              void* d_out, int out_size)
{
    const float* x    = (const float*)d_in[0];
    const float* Wq   = (const float*)d_in[1];
    const float* bq   = (const float*)d_in[2];
    const float* Wk   = (const float*)d_in[3];
    const float* bk   = (const float*)d_in[4];
    const float* Wv   = (const float*)d_in[5];
    const float* bv   = (const float*)d_in[6];
    const float* Wo   = (const float*)d_in[7];
    const float* bo   = (const float*)d_in[8];
    const float* Wvec = (const float*)d_in[9];
    const float* ad   = (const float*)d_in[10];
    const float* an   = (const float*)d_in[11];
    const float* Wg   = (const float*)d_in[12];
    const float* bg   = (const float*)d_in[13];
    float* out = (float*)d_out;

    prep_bf16<<<1024, 256>>>(x, Wq, Wk, Wv, Wvec, Wo, Wg);
    proj_mma <<<384 + 1024, 256>>>(x, bq, bk, bv);
    attn_kernel<<<dim3(NN / 32, NH, BB), 128>>>(out);
    epi_mma<<<dim3(BN / 64, 8), 256>>>(x, bo, bg, ad, an, out);
}

// round 16
// speedup vs baseline: 1.1581x; 1.0084x over previous
#include <cuda_runtime.h>
#include <cuda_bf16.h>
#include <math.h>

#define BB   2
#define NN   2048
#define HH   256
#define NH   8
#define HD   32
#define WIN  32
#define WLEN 65
#define BN   (BB*NN)                       /* 4096 rows */
#define AOFF ((size_t)BB*NN*4*HH)          /* x_final elements = 4194304 */

// ---------------- scratch (static device globals; no allocation) ------------
__device__ __align__(16) float g_q[BN*HH];
__device__ __align__(16) float g_k[BN*HH];
__device__ __align__(16) float g_v[BN*HH];
__device__ __align__(16) float g_vd[BN*HH];
__device__ __align__(16) float g_vn[BN*HH];
__device__ __align__(16) float g_vaggr[BN*3*HH];
__device__ __align__(16) float g_xout[BN*HH];
// bf16 packed (2 per unsigned word)
__device__ __align__(16) unsigned g_bx[BN*4*HH/2];
__device__ __align__(16) unsigned g_bWq[HH*HH/2];
__device__ __align__(16) unsigned g_bWk[HH*HH/2];
__device__ __align__(16) unsigned g_bWv[HH*HH/2];
__device__ __align__(16) unsigned g_bWvec[HH*2*HH/2];
__device__ __align__(16) unsigned g_bWo[HH*3*HH/2];
__device__ __align__(16) unsigned g_bWg[2*HH*HH/2];
__device__ __align__(16) unsigned g_bv[BN*HH/2];
__device__ __align__(16) unsigned g_bxout[BN*HH/2];
__device__ __align__(16) unsigned g_bvd[BN*HH/2];
__device__ __align__(16) unsigned g_bvn[BN*HH/2];

// ---------------- helpers ----------------------------------------------------
__device__ __forceinline__ unsigned pk(float lo, float hi) {
    unsigned r; asm("cvt.rn.bf16x2.f32 %0, %1, %2;" : "=r"(r) : "f"(hi), "f"(lo));
    return r;
}
__device__ __forceinline__ unsigned su(const void* p) {
    return (unsigned)__cvta_generic_to_shared(p);
}
__device__ __forceinline__ void cpa16(unsigned saddr, const void* gptr) {
    asm volatile("cp.async.ca.shared.global [%0], [%1], 16;" :: "r"(saddr), "l"(gptr));
}
#define CPA_COMMIT asm volatile("cp.async.commit_group;" ::: "memory")
#define CPA_WAIT0  asm volatile("cp.async.wait_group 0;"  ::: "memory")
#define CPA_WAIT1  asm volatile("cp.async.wait_group 1;"  ::: "memory")
__device__ __forceinline__ void ldsm4(unsigned* r, unsigned a) {
    asm volatile("ldmatrix.sync.aligned.m8n8.x4.shared.b16 {%0,%1,%2,%3},[%4];"
        : "=r"(r[0]), "=r"(r[1]), "=r"(r[2]), "=r"(r[3]) : "r"(a));
}
__device__ __forceinline__ void ldsm4t(unsigned* r, unsigned a) {
    asm volatile("ldmatrix.sync.aligned.m8n8.x4.trans.shared.b16 {%0,%1,%2,%3},[%4];"
        : "=r"(r[0]), "=r"(r[1]), "=r"(r[2]), "=r"(r[3]) : "r"(a));
}
__device__ __forceinline__ void mma_bf16(float* c, const unsigned* a, const unsigned* b) {
    asm volatile("mma.sync.aligned.m16n8k16.row.col.f32.bf16.bf16.f32 "
        "{%0,%1,%2,%3},{%4,%5,%6,%7},{%8,%9},{%0,%1,%2,%3};"
        : "+f"(c[0]), "+f"(c[1]), "+f"(c[2]), "+f"(c[3])
        : "r"(a[0]), "r"(a[1]), "r"(a[2]), "r"(a[3]), "r"(b[0]), "r"(b[1]));
}

// ---------------- kernel 0: bf16 prepack -------------------------------------
__global__ __launch_bounds__(256) void prep_bf16(
    const float* __restrict__ x,
    const float* __restrict__ Wq, const float* __restrict__ Wk,
    const float* __restrict__ Wv, const float* __restrict__ Wvec,
    const float* __restrict__ Wo, const float* __restrict__ Wg)
{
    const int tid = blockIdx.x * 256 + threadIdx.x;
    for (int w = tid; w < 2424832; w += 262144) {
        const float* src; unsigned* dst; int off;
        if (w < 2097152) { src = x; dst = g_bx; off = w; }
        else {
            int u = w - 2097152;
            if      (u <  32768) { src = Wq;   dst = g_bWq;   off = u; }
            else if (u <  65536) { src = Wk;   dst = g_bWk;   off = u -  32768; }
            else if (u <  98304) { src = Wv;   dst = g_bWv;   off = u -  65536; }
            else if (u < 163840) { src = Wvec; dst = g_bWvec; off = u -  98304; }
            else if (u < 262144) { src = Wo;   dst = g_bWo;   off = u - 163840; }
            else                 { src = Wg;   dst = g_bWg;   off = u - 262144; }
        }
        float2 v = *(const float2*)(src + 2 * (size_t)off);
        dst[off] = pk(v.x, v.y);
    }
}

// ---------------- smem layout structs (3-stage) ------------------------------
struct QkvS { unsigned As[3][64][20]; unsigned Bs[3][32][68]; };     // 41472 B
struct VecS { unsigned As[3][96][20]; unsigned Bs[3][2][32][20]; };  // 38400 B
struct OutS { unsigned As[3][64][12]; unsigned Bs[3][3][16][36]; };  // 29952 B
struct GateS{ unsigned As[3][64][20]; unsigned Bs[3][32][36]; };     // 29184 B

#define PROJ_SMEM (sizeof(QkvS) > sizeof(VecS) ? sizeof(QkvS) : sizeof(VecS))
#define EPI_SMEM  (sizeof(OutS) > sizeof(GateS) ? sizeof(OutS) : sizeof(GateS))

// wait helper: full wait on the LAST chunk (its group is the newest pending one;
// wait_group 1 would let compute race the in-flight fill — the R15 bug).
#define CPA_WAIT_PIPE(kc, last) do { if ((kc) < (last)) { CPA_WAIT1; } else { CPA_WAIT0; } } while (0)

// ---------------- kernel 1: fused projections (qkv + vec), 3-stage -----------
__global__ __launch_bounds__(256) void proj_mma(
    const float* __restrict__ x,
    const float* __restrict__ bq, const float* __restrict__ bk,
    const float* __restrict__ bv)
{
    __shared__ __align__(16) char smraw[PROJ_SMEM];
    const int t = threadIdx.x, lane = t & 31, wp = t >> 5;
    const int g = lane >> 2, tg = lane & 3;
    const int tl = lane >> 3, trow = lane & 7;
    const int aRow  = (tl & 1) * 8 + trow;
    const int aColW = (tl >> 1) * 4;
    const int bid = blockIdx.x;

    if (bid < 384) {
        // ===== qkv: BM=64, BN=128, K=256, BK=32 (8 chunks) =====
        QkvS& S = *(QkvS*)smraw;
        const int wm = wp >> 2, wn = wp & 3;
        const int nt = bid >> 6;
        const int rb = (bid & 63) * 64;
        const unsigned* bW = (nt < 2) ? g_bWq : (nt < 4) ? g_bWk : g_bWv;
        const int cb = (nt & 1) * 128;

        float C[2][4][4];
#pragma unroll
        for (int mi = 0; mi < 2; mi++)
#pragma unroll
            for (int nj = 0; nj < 4; nj++)
#pragma unroll
                for (int e = 0; e < 4; e++) C[mi][nj][e] = 0.f;

        const int ar = t >> 2, ac = (t & 3) * 4;
        auto issue = [&](int kc, int buf) {
            cpa16(su(&S.As[buf][ar][ac]),
                  g_bx + ((size_t)(rb + ar) * 4) * 128 + kc * 16 + ac);
#pragma unroll
            for (int i = 0; i < 2; i++) {
                int idx = t + i * 256; int r = idx >> 4, c = idx & 15;
                cpa16(su(&S.Bs[buf][r][c * 4]),
                      bW + (size_t)(kc * 32 + r) * 128 + (cb >> 1) + c * 4);
            }
            CPA_COMMIT;
        };
        issue(0, 0); issue(1, 1);
        for (int kc = 0; kc < 8; kc++) {
            const int buf = kc % 3;
            CPA_WAIT_PIPE(kc, 7); __syncthreads();
            if (kc < 6) issue(kc + 2, (kc + 2) % 3);
#pragma unroll
            for (int kk = 0; kk < 32; kk += 16) {
                const int kkW = kk >> 1;
                unsigned a[2][4], bfr[2][4];
#pragma unroll
                for (int mi = 0; mi < 2; mi++)
                    ldsm4(a[mi], su(&S.As[buf][wm * 32 + mi * 16 + aRow][aColW + kkW]));
#pragma unroll
                for (int ns = 0; ns < 2; ns++)
                    ldsm4t(bfr[ns], su(&S.Bs[buf][kk + aRow][wn * 16 + ns * 8 + aColW]));
#pragma unroll
                for (int mi = 0; mi < 2; mi++)
#pragma unroll
                    for (int nj = 0; nj < 4; nj++)
                        mma_bf16(C[mi][nj], a[mi], &bfr[nj >> 1][(nj & 1) * 2]);
            }
        }
        const float* bb = (nt < 2) ? bq : (nt < 4) ? bk : bv;
        float* op = (nt < 2) ? g_q : (nt < 4) ? g_k : g_v;
        const bool isV = (nt >= 4);
#pragma unroll
        for (int mi = 0; mi < 2; mi++)
#pragma unroll
            for (int nj = 0; nj < 4; nj++) {
                int row = rb + wm * 32 + mi * 16 + g;
                int col = cb + wn * 32 + nj * 8 + 2 * tg;
                float b0 = bb[col], b1 = bb[col + 1];
                float r0 = C[mi][nj][0] + b0, r1 = C[mi][nj][1] + b1;
                float r2 = C[mi][nj][2] + b0, r3 = C[mi][nj][3] + b1;
                *(float2*)(op + (size_t)row * 256 + col) = make_float2(r0, r1);
                *(float2*)(op + (size_t)(row + 8) * 256 + col) = make_float2(r2, r3);
                if (isV) {
                    g_bv[((size_t)row * 256 + col) >> 1] = pk(r0, r1);
                    g_bv[((size_t)(row + 8) * 256 + col) >> 1] = pk(r2, r3);
                }
            }
    } else {
        // ===== vec: BM=96, 2 sets x 32 cols, K=256, BK=32 (8 chunks) =====
        VecS& S = *(VecS*)smraw;
        const int vid = bid - 384;
        const int mb = vid >> 3;
        const int n0 = (vid & 7) * 32;
        const int rb3 = mb * 96, bn0 = mb * 32;
        const int wm = wp % 3, wn = wp / 3;

        float C[2][2][2][4];
#pragma unroll
        for (int s = 0; s < 2; s++)
#pragma unroll
            for (int mi = 0; mi < 2; mi++)
#pragma unroll
                for (int ni = 0; ni < 2; ni++)
#pragma unroll
                    for (int e = 0; e < 4; e++) C[s][mi][ni][e] = 0.f;

        auto issue = [&](int kc, int buf) {
#pragma unroll
            for (int i = 0; i < 2; i++) {
                int idx = t + i * 256;
                if (idx < 384) {
                    int r = idx >> 2, c = idx & 3;
                    int R = rb3 + r, bn = R / 3, cch = R - bn * 3;
                    cpa16(su(&S.As[buf][r][c * 4]),
                          g_bx + ((size_t)bn * 4 + 1 + cch) * 128 + kc * 16 + c * 4);
                }
            }
            {
                int s = t >> 7, rem = t & 127, r = rem >> 2, c = rem & 3;
                cpa16(su(&S.Bs[buf][s][r][c * 4]),
                      g_bWvec + (size_t)(kc * 32 + r) * 256 + s * 128 + (n0 >> 1) + c * 4);
            }
            CPA_COMMIT;
        };
        issue(0, 0);

        // fp32 vec_norm (exact inputs), n0==0 blocks only — overlaps fill
        if (n0 == 0) {
            __nv_bfloat16* bvn = (__nv_bfloat16*)g_bvn;
            for (int idx = t; idx < 32 * 256; idx += 256) {
                int G = idx >> 8, tt = idx & 255;
                size_t base = ((size_t)(bn0 + G) * 4 + 1) * 256 + tt;
                float v0 = x[base], v1 = x[base + 256], v2 = x[base + 512];
                float vn = sqrtf(v0*v0 + v1*v1 + v2*v2);
                size_t el = (size_t)(bn0 + G) * 256 + tt;
                g_vn[el] = vn;
                bvn[el] = __float2bfloat16(vn);
            }
        }
        issue(1, 1);

        for (int kc = 0; kc < 8; kc++) {
            const int buf = kc % 3;
            CPA_WAIT_PIPE(kc, 7); __syncthreads();
            if (kc < 6) issue(kc + 2, (kc + 2) % 3);
            if (wp < 6) {
#pragma unroll
                for (int kk = 0; kk < 32; kk += 16) {
                    const int kkW = kk >> 1;
                    unsigned a[2][4], bfr[2][4];
#pragma unroll
                    for (int mi = 0; mi < 2; mi++)
                        ldsm4(a[mi], su(&S.As[buf][wm * 32 + mi * 16 + aRow][aColW + kkW]));
#pragma unroll
                    for (int s = 0; s < 2; s++)
                        ldsm4t(bfr[s], su(&S.Bs[buf][s][kk + aRow][wn * 8 + aColW]));
#pragma unroll
                    for (int s = 0; s < 2; s++)
#pragma unroll
                        for (int mi = 0; mi < 2; mi++)
#pragma unroll
                            for (int ni = 0; ni < 2; ni++)
                                mma_bf16(C[s][mi][ni], a[mi], &bfr[s][ni * 2]);
                }
            }
        }
        __syncthreads();
        float (*pr)[33] = (float(*)[33])S.As;
        if (wp < 6) {
#pragma unroll
            for (int mi = 0; mi < 2; mi++)
#pragma unroll
                for (int ni = 0; ni < 2; ni++) {
                    int r0 = wm * 32 + mi * 16 + g, c0 = wn * 16 + ni * 8 + 2 * tg;
                    pr[r0][c0]       = C[0][mi][ni][0] * C[1][mi][ni][0];
                    pr[r0][c0 + 1]   = C[0][mi][ni][1] * C[1][mi][ni][1];
                    pr[r0 + 8][c0]   = C[0][mi][ni][2] * C[1][mi][ni][2];
                    pr[r0 + 8][c0+1] = C[0][mi][ni][3] * C[1][mi][ni][3];
                }
        }
        __syncthreads();
        __nv_bfloat16* bvd = (__nv_bfloat16*)g_bvd;
        for (int idx = t; idx < 1024; idx += 256) {
            int G = idx >> 5, tt = idx & 31;
            float val = pr[3*G][tt] + pr[3*G+1][tt] + pr[3*G+2][tt];
            size_t el = (size_t)(bn0 + G) * 256 + n0 + tt;
            g_vd[el] = val;
            bvd[el] = __float2bfloat16(val);
        }
    }
}

// ---------------- kernel 2: attention — scores fp32, aggregation via MMA -----
__global__ __launch_bounds__(128) void attn_kernel(float* __restrict__ out)
{
    __shared__ __align__(16) unsigned smU[96 * 68];
    __shared__ __align__(16) unsigned wband[32][52];
    const int tid  = threadIdx.x;
    const int lane = tid & 31;
    const int wp   = tid >> 5;
    const int g = lane >> 2, tg = lane & 3;
    const int tl = lane >> 3, trow = lane & 7;
    const int aRow  = (tl & 1) * 8 + trow;
    const int aColW = (tl >> 1) * 4;
    const int i0   = blockIdx.x * 32;
    const int hh   = blockIdx.y;
    const int b    = blockIdx.z;
    const int jb   = i0 - WIN;

    float (*ks)[36] = (float(*)[36])smU;
    float (*qs)[32] = (float(*)[32])(smU + 96 * 36);

    const float* kg = g_k + (size_t)b * NN * HH + hh * HD;
    for (int idx = tid; idx < 96 * 8; idx += 128) {
        int r = idx >> 3, d4 = (idx & 7) * 4, j = jb + r;
        float4 v = make_float4(0.f, 0.f, 0.f, 0.f);
        if ((unsigned)j < NN) v = *(const float4*)(kg + (size_t)j * HH + d4);
        *(float4*)&ks[r][d4] = v;
    }
    const float* qg = g_q + ((size_t)b * NN + i0) * HH + hh * HD;
    for (int idx = tid; idx < 32 * 8; idx += 128) {
        int r = idx >> 3, d4 = (idx & 7) * 4;
        *(float4*)&qs[r][d4] = *(const float4*)(qg + (size_t)r * HH + d4);
    }
    for (int idx = tid; idx < 32 * 52; idx += 128) ((unsigned*)wband)[idx] = 0;
    __syncthreads();

    const float scale = 0.17677669529663687f;
    for (int ql = 0; ql < 8; ql++) {
        const int q = wp * 8 + ql;
        const int i = i0 + q;
        float s0 = 0.f, s1 = 0.f;
        {
            const float* qr = qs[q];
            const float* ka = ks[q + lane];
            const float* kb = ks[q + lane + 32];
#pragma unroll
            for (int d4 = 0; d4 < 32; d4 += 4) {
                float4 qv = *(const float4*)(qr + d4);
                float4 a4 = *(const float4*)(ka + d4);
                float4 b4 = *(const float4*)(kb + d4);
                s0 = fmaf(qv.x,a4.x, fmaf(qv.y,a4.y, fmaf(qv.z,a4.z, fmaf(qv.w,a4.w, s0))));
                s1 = fmaf(qv.x,b4.x, fmaf(qv.y,b4.y, fmaf(qv.z,b4.z, fmaf(qv.w,b4.w, s1))));
            }
        }
        float e2 = 0.f;
        if (lane == 0) {
            const float* qr = qs[q];
            const float* kc = ks[q + 64];
            float s2 = 0.f;
#pragma unroll
            for (int d4 = 0; d4 < 32; d4 += 4) {
                float4 qv = *(const float4*)(qr + d4);
                float4 c4 = *(const float4*)(kc + d4);
                s2 = fmaf(qv.x,c4.x, fmaf(qv.y,c4.y, fmaf(qv.z,c4.z, fmaf(qv.w,c4.w, s2))));
            }
            e2 = __expf(s2 * scale);
        }
        float e0 = __expf(s0 * scale), e1 = __expf(s1 * scale);
        float sm = e0 + e1 + e2;
#pragma unroll
        for (int o = 16; o; o >>= 1) sm += __shfl_xor_sync(0xffffffffu, sm, o);
        float inv = 1.f / sm;
        float p0 = e0 * inv, p1 = e1 * inv;
        float* ab = out + AOFF + (((size_t)(b * NH + hh)) * NN + i) * WLEN;
        ab[lane]      = p0;
        ab[lane + 32] = p1;
        __nv_bfloat16* wb = ((__nv_bfloat16*)wband) + q * 104;
        wb[q + lane]      = __float2bfloat16(p0);
        wb[q + lane + 32] = __float2bfloat16(p1);
        if (lane == 0) { float p2 = e2 * inv; ab[64] = p2; wb[q + 64] = __float2bfloat16(p2); }
    }
    __syncthreads();

    unsigned (*Vw)[68] = (unsigned(*)[68])smU;
    const bool boundary = (jb < 0) || (jb + 95 >= NN);
    if (boundary) {
        for (int idx = tid; idx < 96 * 68; idx += 128) smU[idx] = 0;
        __syncthreads();
    }
#pragma unroll
    for (int i = 0; i < 12; i++) {
        int idx = tid + i * 128;
        int r = idx >> 4, ch = idx & 15;
        int j = jb + r;
        if ((unsigned)j < NN) {
            const unsigned* src;
            if (ch < 4)
                src = g_bv + ((size_t)b * NN + j) * 128 + hh * 16 + ch * 4;
            else {
                int c = (ch - 4) >> 2, cc = (ch - 4) & 3;
                src = g_bx + (((size_t)b * NN + j) * 4 + 1 + c) * 128 + hh * 16 + cc * 4;
            }
            cpa16(su(&Vw[r][ch * 4]), src);
        }
    }
    CPA_COMMIT; CPA_WAIT0;
    __syncthreads();

    const int wm2 = wp & 1, wn2 = wp >> 1;
    float C[8][4];
#pragma unroll
    for (int f = 0; f < 8; f++)
#pragma unroll
        for (int e = 0; e < 4; e++) C[f][e] = 0.f;

#pragma unroll
    for (int kc = 0; kc < 6; kc++) {
        unsigned a[4];
        ldsm4(a, su(&wband[wm2 * 16 + aRow][aColW + kc * 8]));
#pragma unroll
        for (int ns = 0; ns < 4; ns++) {
            unsigned bf[4];
            ldsm4t(bf, su(&Vw[kc * 16 + aRow][wn2 * 32 + ns * 8 + aColW]));
            mma_bf16(C[ns * 2 + 0], a, &bf[0]);
            mma_bf16(C[ns * 2 + 1], a, &bf[2]);
        }
    }

#pragma unroll
    for (int ns = 0; ns < 4; ns++)
#pragma unroll
        for (int h = 0; h < 2; h++) {
            const float* frag = C[ns * 2 + h];
            int colb = wn2 * 64 + ns * 16 + h * 8 + 2 * tg;
#pragma unroll
            for (int hf = 0; hf < 2; hf++) {
                int row = i0 + wm2 * 16 + g + hf * 8;
                float c0 = frag[hf * 2], c1 = frag[hf * 2 + 1];
                if (colb < 32) {
                    size_t el = ((size_t)b * NN + row) * 256 + hh * HD + colb;
                    *(float2*)(g_xout + el) = make_float2(c0, c1);
                    g_bxout[el >> 1] = pk(c0, c1);
                } else {
                    int c = (colb - 32) >> 5, dd = (colb - 32) & 31;
                    *(float2*)(g_vaggr + (((size_t)(b * NN + row)) * 3 + c) * 256 + hh * HD + dd)
                        = make_float2(c0, c1);
                }
            }
        }
}

// ---------------- kernel 3: fused epilogue (out ∪ gate), 3-stage -------------
__global__ __launch_bounds__(256) void epi_mma(
    const float* __restrict__ x,
    const float* __restrict__ bo, const float* __restrict__ bg,
    const float* __restrict__ alpha_dot, const float* __restrict__ alpha_norm,
    float* __restrict__ out)
{
    __shared__ __align__(16) char smraw[EPI_SMEM];
    const int t = threadIdx.x, lane = t & 31, wp = t >> 5;
    const int g = lane >> 2, tg = lane & 3;
    const int wm = wp >> 2, wn = wp & 3;
    const int tl = lane >> 3, trow = lane & 7;
    const int aRow  = (tl & 1) * 8 + trow;
    const int aColW = (tl >> 1) * 4;
    const int rb = blockIdx.x * 64;

    if (blockIdx.y < 4) {
        // ===== out: BM=64, 3 sets x 64 cols, K=256, BK=16 (16 chunks) =====
        OutS& S = *(OutS*)smraw;
        const int cb = blockIdx.y * 64;

        float C[3][2][2][4];
#pragma unroll
        for (int s = 0; s < 3; s++)
#pragma unroll
            for (int mi = 0; mi < 2; mi++)
#pragma unroll
                for (int ni = 0; ni < 2; ni++)
#pragma unroll
                    for (int e = 0; e < 4; e++) C[s][mi][ni][e] = 0.f;

        auto issue = [&](int kc, int buf) {
            if (t < 128) {
                int r = t >> 1, c = (t & 1) * 4;
                cpa16(su(&S.As[buf][r][c]),
                      g_bxout + (size_t)(rb + r) * 128 + kc * 8 + c);
            }
#pragma unroll
            for (int i = 0; i < 2; i++) {
                int idx = t + i * 256;
                if (idx < 384) {
                    int s = idx >> 7, rem = idx & 127, r = rem >> 3, c = rem & 7;
                    cpa16(su(&S.Bs[buf][s][r][c * 4]),
                          g_bWo + (size_t)(kc * 16 + r) * 384 + ((s * 256 + cb) >> 1) + c * 4);
                }
            }
            CPA_COMMIT;
        };
        issue(0, 0); issue(1, 1);
        for (int kc = 0; kc < 16; kc++) {
            const int buf = kc % 3;
            CPA_WAIT_PIPE(kc, 15); __syncthreads();
            if (kc < 14) issue(kc + 2, (kc + 2) % 3);
            unsigned a[2][4], bfr[3][4];
#pragma unroll
            for (int mi = 0; mi < 2; mi++)
                ldsm4(a[mi], su(&S.As[buf][wm * 32 + mi * 16 + aRow][aColW]));
#pragma unroll
            for (int s = 0; s < 3; s++)
                ldsm4t(bfr[s], su(&S.Bs[buf][s][aRow][wn * 8 + aColW]));
#pragma unroll
            for (int s = 0; s < 3; s++)
#pragma unroll
                for (int mi = 0; mi < 2; mi++)
#pragma unroll
                    for (int ni = 0; ni < 2; ni++)
                        mma_bf16(C[s][mi][ni], a[mi], &bfr[s][ni * 2]);
        }
#pragma unroll
        for (int mi = 0; mi < 2; mi++)
#pragma unroll
            for (int ni = 0; ni < 2; ni++) {
                int col = cb + wn * 16 + ni * 8 + 2 * tg;
                float b0 = bo[col],       b1 = bo[col + 1];
                float b2 = bo[col + 256], b3 = bo[col + 257];
                float b4 = bo[col + 512], b5 = bo[col + 513];
#pragma unroll
                for (int hf = 0; hf < 2; hf++) {
                    int row = rb + wm * 32 + mi * 16 + g + hf * 8;
                    int e = hf * 2;
                    float2 vd = *(const float2*)(g_vd + (size_t)row * 256 + col);
                    float2 vn = *(const float2*)(g_vn + (size_t)row * 256 + col);
                    float rx = vd.x * (C[0][mi][ni][e]   + b0) + vn.x * (C[1][mi][ni][e]   + b2) + (C[2][mi][ni][e]   + b4);
                    float ry = vd.y * (C[0][mi][ni][e+1] + b1) + vn.y * (C[1][mi][ni][e+1] + b3) + (C[2][mi][ni][e+1] + b5);
                    *(float2*)(out + (size_t)row * 1024 + col) = make_float2(rx, ry);
                }
            }
    } else {
        // ===== gate: BM=64, BN=64, K=512, BK=32 (16 chunks) =====
        GateS& S = *(GateS*)smraw;
        const int cb = (blockIdx.y - 4) * 64;
        const float adv = *alpha_dot, anv = *alpha_norm;

        float C[2][2][2][4];
#pragma unroll
        for (int p = 0; p < 2; p++)
#pragma unroll
            for (int mi = 0; mi < 2; mi++)
#pragma unroll
                for (int ni = 0; ni < 2; ni++)
#pragma unroll
                    for (int e = 0; e < 4; e++) C[p][mi][ni][e] = 0.f;

        const int ar = t >> 2, ac = (t & 3) * 4;
        auto issue = [&](int kc, int buf) {
            const unsigned* srcA = (kc < 8) ? g_bvd : g_bvn;
            cpa16(su(&S.As[buf][ar][ac]),
                  srcA + (size_t)(rb + ar) * 128 + (kc & 7) * 16 + ac);
            {
                int r = t >> 3, c = t & 7;
                cpa16(su(&S.Bs[buf][r][c * 4]),
                      g_bWg + (size_t)(kc * 32 + r) * 128 + (cb >> 1) + c * 4);
            }
            CPA_COMMIT;
        };
        issue(0, 0); issue(1, 1);
        for (int kc = 0; kc < 16; kc++) {
            const int buf = kc % 3;
            const int p = kc >> 3;
            CPA_WAIT_PIPE(kc, 15); __syncthreads();
            if (kc < 14) issue(kc + 2, (kc + 2) % 3);
#pragma unroll
            for (int kk = 0; kk < 32; kk += 16) {
                const int kkW = kk >> 1;
                unsigned a[2][4], bfr[4];
#pragma unroll
                for (int mi = 0; mi < 2; mi++)
                    ldsm4(a[mi], su(&S.As[buf][wm * 32 + mi * 16 + aRow][aColW + kkW]));
                ldsm4t(bfr, su(&S.Bs[buf][kk + aRow][wn * 8 + aColW]));
#pragma unroll
                for (int mi = 0; mi < 2; mi++)
#pragma unroll
                    for (int ni = 0; ni < 2; ni++)
                        mma_bf16(C[p][mi][ni], a[mi], &bfr[ni * 2]);
            }
        }
#pragma unroll
        for (int mi = 0; mi < 2; mi++)
#pragma unroll
            for (int ni = 0; ni < 2; ni++) {
                int col = cb + wn * 16 + ni * 8 + 2 * tg;
                float bg0 = bg[col], bg1 = bg[col + 1];
#pragma unroll
                for (int hf = 0; hf < 2; hf++) {
                    int row = rb + wm * 32 + mi * 16 + g + hf * 8;
                    int e = hf * 2;
                    float z0 = adv * C[0][mi][ni][e]   + anv * C[1][mi][ni][e]   + bg0;
                    float z1 = adv * C[0][mi][ni][e+1] + anv * C[1][mi][ni][e+1] + bg1;
                    float g0 = 1.f / (1.f + expf(-z0));
                    float g1 = 1.f / (1.f + expf(-z1));
#pragma unroll
                    for (int c = 0; c < 3; c++) {
                        float2 va = *(const float2*)(g_vaggr + ((size_t)row * 3 + c) * 256 + col);
                        size_t oi = ((size_t)row * 4 + 1 + c) * 256 + col;
                        float2 xv = *(const float2*)(x + oi);
                        *(float2*)(out + oi) = make_float2(g0 * va.x + xv.x, g1 * va.y + xv.y);
                    }
                }
            }
    }
}

// ---------------- launch ----------------------------------------------------
extern "C" void kernel_launch(void* const* d_in, const int* in_sizes, int n_in,
                              void* d_out, int out_size)
{
    const float* x    = (const float*)d_in[0];
    const float* Wq   = (const float*)d_in[1];
    const float* bq   = (const float*)d_in[2];
    const float* Wk   = (const float*)d_in[3];
    const float* bk   = (const float*)d_in[4];
    const float* Wv   = (const float*)d_in[5];
    const float* bv   = (const float*)d_in[6];
    const float* Wo   = (const float*)d_in[7];
    const float* bo   = (const float*)d_in[8];
    const float* Wvec = (const float*)d_in[9];
    const float* ad   = (const float*)d_in[10];
    const float* an   = (const float*)d_in[11];
    const float* Wg   = (const float*)d_in[12];
    const float* bg   = (const float*)d_in[13];
    float* out = (float*)d_out;

    prep_bf16<<<1024, 256>>>(x, Wq, Wk, Wv, Wvec, Wo, Wg);
    proj_mma <<<384 + 1024, 256>>>(x, bq, bk, bv);
    attn_kernel<<<dim3(NN / 32, NH, BB), 128>>>(out);
    epi_mma<<<dim3(BN / 64, 8), 256>>>(x, bo, bg, ad, an, out);
}

// round 17
// speedup vs baseline: 1.1607x; 1.0022x over previous
#include <cuda_runtime.h>
#include <cuda_bf16.h>
#include <math.h>

#define BB   2
#define NN   2048
#define HH   256
#define NH   8
#define HD   32
#define WIN  32
#define WLEN 65
#define BN   (BB*NN)                       /* 4096 rows */
#define AOFF ((size_t)BB*NN*4*HH)          /* x_final elements = 4194304 */

// ---------------- scratch (static device globals; no allocation) ------------
__device__ __align__(16) float g_q[BN*HH];
__device__ __align__(16) float g_k[BN*HH];
__device__ __align__(16) float g_v[BN*HH];
__device__ __align__(16) float g_vd[BN*HH];
__device__ __align__(16) float g_vn[BN*HH];
__device__ __align__(16) float g_vaggr[BN*3*HH];
__device__ __align__(16) float g_xout[BN*HH];
// bf16 packed (2 per unsigned word)
__device__ __align__(16) unsigned g_bx[BN*4*HH/2];
__device__ __align__(16) unsigned g_bWq[HH*HH/2];
__device__ __align__(16) unsigned g_bWk[HH*HH/2];
__device__ __align__(16) unsigned g_bWv[HH*HH/2];
__device__ __align__(16) unsigned g_bWvec[HH*2*HH/2];
__device__ __align__(16) unsigned g_bWo[HH*3*HH/2];
__device__ __align__(16) unsigned g_bWg[2*HH*HH/2];
__device__ __align__(16) unsigned g_bv[BN*HH/2];
__device__ __align__(16) unsigned g_bxout[BN*HH/2];
__device__ __align__(16) unsigned g_bvd[BN*HH/2];
__device__ __align__(16) unsigned g_bvn[BN*HH/2];

// ---------------- helpers ----------------------------------------------------
__device__ __forceinline__ unsigned pk(float lo, float hi) {
    unsigned r; asm("cvt.rn.bf16x2.f32 %0, %1, %2;" : "=r"(r) : "f"(hi), "f"(lo));
    return r;
}
__device__ __forceinline__ unsigned su(const void* p) {
    return (unsigned)__cvta_generic_to_shared(p);
}
__device__ __forceinline__ void cpa16(unsigned saddr, const void* gptr) {
    asm volatile("cp.async.ca.shared.global [%0], [%1], 16;" :: "r"(saddr), "l"(gptr));
}
#define CPA_COMMIT asm volatile("cp.async.commit_group;" ::: "memory")
#define CPA_WAIT0  asm volatile("cp.async.wait_group 0;"  ::: "memory")
#define CPA_WAIT1  asm volatile("cp.async.wait_group 1;"  ::: "memory")
__device__ __forceinline__ void ldsm4(unsigned* r, unsigned a) {
    asm volatile("ldmatrix.sync.aligned.m8n8.x4.shared.b16 {%0,%1,%2,%3},[%4];"
        : "=r"(r[0]), "=r"(r[1]), "=r"(r[2]), "=r"(r[3]) : "r"(a));
}
__device__ __forceinline__ void ldsm4t(unsigned* r, unsigned a) {
    asm volatile("ldmatrix.sync.aligned.m8n8.x4.trans.shared.b16 {%0,%1,%2,%3},[%4];"
        : "=r"(r[0]), "=r"(r[1]), "=r"(r[2]), "=r"(r[3]) : "r"(a));
}
__device__ __forceinline__ void mma_bf16(float* c, const unsigned* a, const unsigned* b) {
    asm volatile("mma.sync.aligned.m16n8k16.row.col.f32.bf16.bf16.f32 "
        "{%0,%1,%2,%3},{%4,%5,%6,%7},{%8,%9},{%0,%1,%2,%3};"
        : "+f"(c[0]), "+f"(c[1]), "+f"(c[2]), "+f"(c[3])
        : "r"(a[0]), "r"(a[1]), "r"(a[2]), "r"(a[3]), "r"(b[0]), "r"(b[1]));
}

// ---------------- kernel 0: bf16 prepack -------------------------------------
__global__ __launch_bounds__(256) void prep_bf16(
    const float* __restrict__ x,
    const float* __restrict__ Wq, const float* __restrict__ Wk,
    const float* __restrict__ Wv, const float* __restrict__ Wvec,
    const float* __restrict__ Wo, const float* __restrict__ Wg)
{
    const int tid = blockIdx.x * 256 + threadIdx.x;
    for (int w = tid; w < 2424832; w += 262144) {
        const float* src; unsigned* dst; int off;
        if (w < 2097152) { src = x; dst = g_bx; off = w; }
        else {
            int u = w - 2097152;
            if      (u <  32768) { src = Wq;   dst = g_bWq;   off = u; }
            else if (u <  65536) { src = Wk;   dst = g_bWk;   off = u -  32768; }
            else if (u <  98304) { src = Wv;   dst = g_bWv;   off = u -  65536; }
            else if (u < 163840) { src = Wvec; dst = g_bWvec; off = u -  98304; }
            else if (u < 262144) { src = Wo;   dst = g_bWo;   off = u - 163840; }
            else                 { src = Wg;   dst = g_bWg;   off = u - 262144; }
        }
        float2 v = *(const float2*)(src + 2 * (size_t)off);
        dst[off] = pk(v.x, v.y);
    }
}

// ---------------- smem layout structs (3-stage) ------------------------------
struct QkvS { unsigned As[3][64][20]; unsigned Bs[3][32][68]; };     // 41472 B
struct VecS { unsigned As[3][96][20]; unsigned Bs[3][2][32][20]; };  // 38400 B
struct OutS { unsigned As[3][64][12]; unsigned Bs[3][3][16][36]; };  // 29952 B
struct GateS{ unsigned As[3][64][20]; unsigned Bs[3][32][36]; };     // 29184 B

#define PROJ_SMEM (sizeof(QkvS) > sizeof(VecS) ? sizeof(QkvS) : sizeof(VecS))
#define EPI_SMEM  (sizeof(OutS) > sizeof(GateS) ? sizeof(OutS) : sizeof(GateS))

// wait helper: full wait on the LAST chunk (newest pending group — R15 bug fix)
#define CPA_WAIT_PIPE(kc, last) do { if ((kc) < (last)) { CPA_WAIT1; } else { CPA_WAIT0; } } while (0)

// ---------------- kernel 1: fused projections (qkv + vec), 3-stage -----------
__global__ __launch_bounds__(256) void proj_mma(
    const float* __restrict__ x,
    const float* __restrict__ bq, const float* __restrict__ bk,
    const float* __restrict__ bv)
{
    __shared__ __align__(16) char smraw[PROJ_SMEM];
    const int t = threadIdx.x, lane = t & 31, wp = t >> 5;
    const int g = lane >> 2, tg = lane & 3;
    const int tl = lane >> 3, trow = lane & 7;
    const int aRow  = (tl & 1) * 8 + trow;
    const int aColW = (tl >> 1) * 4;
    const int bid = blockIdx.x;

    if (bid < 384) {
        // ===== qkv: BM=64, BN=128, K=256, BK=32 (8 chunks) =====
        QkvS& S = *(QkvS*)smraw;
        const int wm = wp >> 2, wn = wp & 3;
        const int nt = bid >> 6;
        const int rb = (bid & 63) * 64;
        const unsigned* bW = (nt < 2) ? g_bWq : (nt < 4) ? g_bWk : g_bWv;
        const int cb = (nt & 1) * 128;

        float C[2][4][4];
#pragma unroll
        for (int mi = 0; mi < 2; mi++)
#pragma unroll
            for (int nj = 0; nj < 4; nj++)
#pragma unroll
                for (int e = 0; e < 4; e++) C[mi][nj][e] = 0.f;

        const int ar = t >> 2, ac = (t & 3) * 4;
        auto issue = [&](int kc, int buf) {
            cpa16(su(&S.As[buf][ar][ac]),
                  g_bx + ((size_t)(rb + ar) * 4) * 128 + kc * 16 + ac);
#pragma unroll
            for (int i = 0; i < 2; i++) {
                int idx = t + i * 256; int r = idx >> 4, c = idx & 15;
                cpa16(su(&S.Bs[buf][r][c * 4]),
                      bW + (size_t)(kc * 32 + r) * 128 + (cb >> 1) + c * 4);
            }
            CPA_COMMIT;
        };
        issue(0, 0); issue(1, 1);
        for (int kc = 0; kc < 8; kc++) {
            const int buf = kc % 3;
            CPA_WAIT_PIPE(kc, 7); __syncthreads();
            if (kc < 6) issue(kc + 2, (kc + 2) % 3);
#pragma unroll
            for (int kk = 0; kk < 32; kk += 16) {
                const int kkW = kk >> 1;
                unsigned a[2][4], bfr[2][4];
#pragma unroll
                for (int mi = 0; mi < 2; mi++)
                    ldsm4(a[mi], su(&S.As[buf][wm * 32 + mi * 16 + aRow][aColW + kkW]));
#pragma unroll
                for (int ns = 0; ns < 2; ns++)
                    ldsm4t(bfr[ns], su(&S.Bs[buf][kk + aRow][wn * 16 + ns * 8 + aColW]));
#pragma unroll
                for (int mi = 0; mi < 2; mi++)
#pragma unroll
                    for (int nj = 0; nj < 4; nj++)
                        mma_bf16(C[mi][nj], a[mi], &bfr[nj >> 1][(nj & 1) * 2]);
            }
        }
        // staged, coalesced epilogue: fragments -> smem stage [64][132] fp32
        __syncthreads();
        float (*stg)[132] = (float(*)[132])smraw;   // 33792 B <= 41472
#pragma unroll
        for (int mi = 0; mi < 2; mi++)
#pragma unroll
            for (int nj = 0; nj < 4; nj++) {
                int ur = wm * 32 + mi * 16 + g;
                int uc = wn * 32 + nj * 8 + 2 * tg;
                stg[ur][uc]       = C[mi][nj][0];
                stg[ur][uc + 1]   = C[mi][nj][1];
                stg[ur + 8][uc]   = C[mi][nj][2];
                stg[ur + 8][uc + 1] = C[mi][nj][3];
            }
        __syncthreads();
        const float* bb = (nt < 2) ? bq : (nt < 4) ? bk : bv;
        float* op = (nt < 2) ? g_q : (nt < 4) ? g_k : g_v;
        const bool isV = (nt >= 4);
        for (int it = t; it < 64 * 32; it += 256) {
            int u = it >> 5, c4 = (it & 31) * 4;
            float4 cv = *(const float4*)&stg[u][c4];
            float4 bv4 = *(const float4*)(bb + cb + c4);
            float r0 = cv.x + bv4.x, r1 = cv.y + bv4.y;
            float r2 = cv.z + bv4.z, r3 = cv.w + bv4.w;
            size_t el = (size_t)(rb + u) * 256 + cb + c4;
            *(float4*)(op + el) = make_float4(r0, r1, r2, r3);
            if (isV) {
                uint2 pkd = make_uint2(pk(r0, r1), pk(r2, r3));
                *(uint2*)(g_bv + (el >> 1)) = pkd;
            }
        }
    } else {
        // ===== vec: BM=96, 2 sets x 32 cols, K=256, BK=32 (8 chunks) =====
        VecS& S = *(VecS*)smraw;
        const int vid = bid - 384;
        const int mb = vid >> 3;
        const int n0 = (vid & 7) * 32;
        const int rb3 = mb * 96, bn0 = mb * 32;
        const int wm = wp % 3, wn = wp / 3;

        float C[2][2][2][4];
#pragma unroll
        for (int s = 0; s < 2; s++)
#pragma unroll
            for (int mi = 0; mi < 2; mi++)
#pragma unroll
                for (int ni = 0; ni < 2; ni++)
#pragma unroll
                    for (int e = 0; e < 4; e++) C[s][mi][ni][e] = 0.f;

        auto issue = [&](int kc, int buf) {
#pragma unroll
            for (int i = 0; i < 2; i++) {
                int idx = t + i * 256;
                if (idx < 384) {
                    int r = idx >> 2, c = idx & 3;
                    int R = rb3 + r, bn = R / 3, cch = R - bn * 3;
                    cpa16(su(&S.As[buf][r][c * 4]),
                          g_bx + ((size_t)bn * 4 + 1 + cch) * 128 + kc * 16 + c * 4);
                }
            }
            {
                int s = t >> 7, rem = t & 127, r = rem >> 2, c = rem & 3;
                cpa16(su(&S.Bs[buf][s][r][c * 4]),
                      g_bWvec + (size_t)(kc * 32 + r) * 256 + s * 128 + (n0 >> 1) + c * 4);
            }
            CPA_COMMIT;
        };
        issue(0, 0);

        // fp32 vec_norm (exact inputs), n0==0 blocks only — overlaps fill
        if (n0 == 0) {
            __nv_bfloat16* bvn = (__nv_bfloat16*)g_bvn;
            for (int idx = t; idx < 32 * 256; idx += 256) {
                int G = idx >> 8, tt = idx & 255;
                size_t base = ((size_t)(bn0 + G) * 4 + 1) * 256 + tt;
                float v0 = x[base], v1 = x[base + 256], v2 = x[base + 512];
                float vn = sqrtf(v0*v0 + v1*v1 + v2*v2);
                size_t el = (size_t)(bn0 + G) * 256 + tt;
                g_vn[el] = vn;
                bvn[el] = __float2bfloat16(vn);
            }
        }
        issue(1, 1);

        for (int kc = 0; kc < 8; kc++) {
            const int buf = kc % 3;
            CPA_WAIT_PIPE(kc, 7); __syncthreads();
            if (kc < 6) issue(kc + 2, (kc + 2) % 3);
            if (wp < 6) {
#pragma unroll
                for (int kk = 0; kk < 32; kk += 16) {
                    const int kkW = kk >> 1;
                    unsigned a[2][4], bfr[2][4];
#pragma unroll
                    for (int mi = 0; mi < 2; mi++)
                        ldsm4(a[mi], su(&S.As[buf][wm * 32 + mi * 16 + aRow][aColW + kkW]));
#pragma unroll
                    for (int s = 0; s < 2; s++)
                        ldsm4t(bfr[s], su(&S.Bs[buf][s][kk + aRow][wn * 8 + aColW]));
#pragma unroll
                    for (int s = 0; s < 2; s++)
#pragma unroll
                        for (int mi = 0; mi < 2; mi++)
#pragma unroll
                            for (int ni = 0; ni < 2; ni++)
                                mma_bf16(C[s][mi][ni], a[mi], &bfr[s][ni * 2]);
                }
            }
        }
        __syncthreads();
        float (*pr)[33] = (float(*)[33])S.As;
        if (wp < 6) {
#pragma unroll
            for (int mi = 0; mi < 2; mi++)
#pragma unroll
                for (int ni = 0; ni < 2; ni++) {
                    int r0 = wm * 32 + mi * 16 + g, c0 = wn * 16 + ni * 8 + 2 * tg;
                    pr[r0][c0]       = C[0][mi][ni][0] * C[1][mi][ni][0];
                    pr[r0][c0 + 1]   = C[0][mi][ni][1] * C[1][mi][ni][1];
                    pr[r0 + 8][c0]   = C[0][mi][ni][2] * C[1][mi][ni][2];
                    pr[r0 + 8][c0+1] = C[0][mi][ni][3] * C[1][mi][ni][3];
                }
        }
        __syncthreads();
        __nv_bfloat16* bvd = (__nv_bfloat16*)g_bvd;
        for (int idx = t; idx < 1024; idx += 256) {
            int G = idx >> 5, tt = idx & 31;
            float val = pr[3*G][tt] + pr[3*G+1][tt] + pr[3*G+2][tt];
            size_t el = (size_t)(bn0 + G) * 256 + n0 + tt;
            g_vd[el] = val;
            bvd[el] = __float2bfloat16(val);
        }
    }
}

// ---------------- kernel 2: attention — scores fp32, aggregation via MMA -----
__global__ __launch_bounds__(128) void attn_kernel(float* __restrict__ out)
{
    __shared__ __align__(16) unsigned smU[96 * 68];
    __shared__ __align__(16) unsigned wband[32][52];
    const int tid  = threadIdx.x;
    const int lane = tid & 31;
    const int wp   = tid >> 5;
    const int g = lane >> 2, tg = lane & 3;
    const int tl = lane >> 3, trow = lane & 7;
    const int aRow  = (tl & 1) * 8 + trow;
    const int aColW = (tl >> 1) * 4;
    const int i0   = blockIdx.x * 32;
    const int hh   = blockIdx.y;
    const int b    = blockIdx.z;
    const int jb   = i0 - WIN;

    float (*ks)[36] = (float(*)[36])smU;
    float (*qs)[32] = (float(*)[32])(smU + 96 * 36);

    const float* kg = g_k + (size_t)b * NN * HH + hh * HD;
    for (int idx = tid; idx < 96 * 8; idx += 128) {
        int r = idx >> 3, d4 = (idx & 7) * 4, j = jb + r;
        float4 v = make_float4(0.f, 0.f, 0.f, 0.f);
        if ((unsigned)j < NN) v = *(const float4*)(kg + (size_t)j * HH + d4);
        *(float4*)&ks[r][d4] = v;
    }
    const float* qg = g_q + ((size_t)b * NN + i0) * HH + hh * HD;
    for (int idx = tid; idx < 32 * 8; idx += 128) {
        int r = idx >> 3, d4 = (idx & 7) * 4;
        *(float4*)&qs[r][d4] = *(const float4*)(qg + (size_t)r * HH + d4);
    }
    for (int idx = tid; idx < 32 * 52; idx += 128) ((unsigned*)wband)[idx] = 0;
    __syncthreads();

    const float scale = 0.17677669529663687f;
    for (int ql = 0; ql < 8; ql++) {
        const int q = wp * 8 + ql;
        const int i = i0 + q;
        float s0 = 0.f, s1 = 0.f;
        {
            const float* qr = qs[q];
            const float* ka = ks[q + lane];
            const float* kb = ks[q + lane + 32];
#pragma unroll
            for (int d4 = 0; d4 < 32; d4 += 4) {
                float4 qv = *(const float4*)(qr + d4);
                float4 a4 = *(const float4*)(ka + d4);
                float4 b4 = *(const float4*)(kb + d4);
                s0 = fmaf(qv.x,a4.x, fmaf(qv.y,a4.y, fmaf(qv.z,a4.z, fmaf(qv.w,a4.w, s0))));
                s1 = fmaf(qv.x,b4.x, fmaf(qv.y,b4.y, fmaf(qv.z,b4.z, fmaf(qv.w,b4.w, s1))));
            }
        }
        float e2 = 0.f;
        if (lane == 0) {
            const float* qr = qs[q];
            const float* kc = ks[q + 64];
            float s2 = 0.f;
#pragma unroll
            for (int d4 = 0; d4 < 32; d4 += 4) {
                float4 qv = *(const float4*)(qr + d4);
                float4 c4 = *(const float4*)(kc + d4);
                s2 = fmaf(qv.x,c4.x, fmaf(qv.y,c4.y, fmaf(qv.z,c4.z, fmaf(qv.w,c4.w, s2))));
            }
            e2 = __expf(s2 * scale);
        }
        float e0 = __expf(s0 * scale), e1 = __expf(s1 * scale);
        float sm = e0 + e1 + e2;
#pragma unroll
        for (int o = 16; o; o >>= 1) sm += __shfl_xor_sync(0xffffffffu, sm, o);
        float inv = 1.f / sm;
        float p0 = e0 * inv, p1 = e1 * inv;
        float* ab = out + AOFF + (((size_t)(b * NH + hh)) * NN + i) * WLEN;
        ab[lane]      = p0;
        ab[lane + 32] = p1;
        __nv_bfloat16* wb = ((__nv_bfloat16*)wband) + q * 104;
        wb[q + lane]      = __float2bfloat16(p0);
        wb[q + lane + 32] = __float2bfloat16(p1);
        if (lane == 0) { float p2 = e2 * inv; ab[64] = p2; wb[q + 64] = __float2bfloat16(p2); }
    }
    __syncthreads();

    unsigned (*Vw)[68] = (unsigned(*)[68])smU;
    const bool boundary = (jb < 0) || (jb + 95 >= NN);
    if (boundary) {
        for (int idx = tid; idx < 96 * 68; idx += 128) smU[idx] = 0;
        __syncthreads();
    }
#pragma unroll
    for (int i = 0; i < 12; i++) {
        int idx = tid + i * 128;
        int r = idx >> 4, ch = idx & 15;
        int j = jb + r;
        if ((unsigned)j < NN) {
            const unsigned* src;
            if (ch < 4)
                src = g_bv + ((size_t)b * NN + j) * 128 + hh * 16 + ch * 4;
            else {
                int c = (ch - 4) >> 2, cc = (ch - 4) & 3;
                src = g_bx + (((size_t)b * NN + j) * 4 + 1 + c) * 128 + hh * 16 + cc * 4;
            }
            cpa16(su(&Vw[r][ch * 4]), src);
        }
    }
    CPA_COMMIT; CPA_WAIT0;
    __syncthreads();

    const int wm2 = wp & 1, wn2 = wp >> 1;
    float C[8][4];
#pragma unroll
    for (int f = 0; f < 8; f++)
#pragma unroll
        for (int e = 0; e < 4; e++) C[f][e] = 0.f;

#pragma unroll
    for (int kc = 0; kc < 6; kc++) {
        unsigned a[4];
        ldsm4(a, su(&wband[wm2 * 16 + aRow][aColW + kc * 8]));
#pragma unroll
        for (int ns = 0; ns < 4; ns++) {
            unsigned bf[4];
            ldsm4t(bf, su(&Vw[kc * 16 + aRow][wn2 * 32 + ns * 8 + aColW]));
            mma_bf16(C[ns * 2 + 0], a, &bf[0]);
            mma_bf16(C[ns * 2 + 1], a, &bf[2]);
        }
    }

#pragma unroll
    for (int ns = 0; ns < 4; ns++)
#pragma unroll
        for (int h = 0; h < 2; h++) {
            const float* frag = C[ns * 2 + h];
            int colb = wn2 * 64 + ns * 16 + h * 8 + 2 * tg;
#pragma unroll
            for (int hf = 0; hf < 2; hf++) {
                int row = i0 + wm2 * 16 + g + hf * 8;
                float c0 = frag[hf * 2], c1 = frag[hf * 2 + 1];
                if (colb < 32) {
                    size_t el = ((size_t)b * NN + row) * 256 + hh * HD + colb;
                    *(float2*)(g_xout + el) = make_float2(c0, c1);
                    g_bxout[el >> 1] = pk(c0, c1);
                } else {
                    int c = (colb - 32) >> 5, dd = (colb - 32) & 31;
                    *(float2*)(g_vaggr + (((size_t)(b * NN + row)) * 3 + c) * 256 + hh * HD + dd)
                        = make_float2(c0, c1);
                }
            }
        }
}

// ---------------- kernel 3: fused epilogue (out ∪ gate), staged epilogues ----
__global__ __launch_bounds__(256) void epi_mma(
    const float* __restrict__ x,
    const float* __restrict__ bo, const float* __restrict__ bg,
    const float* __restrict__ alpha_dot, const float* __restrict__ alpha_norm,
    float* __restrict__ out)
{
    __shared__ __align__(16) char smraw[EPI_SMEM];
    const int t = threadIdx.x, lane = t & 31, wp = t >> 5;
    const int g = lane >> 2, tg = lane & 3;
    const int wm = wp >> 2, wn = wp & 3;
    const int tl = lane >> 3, trow = lane & 7;
    const int aRow  = (tl & 1) * 8 + trow;
    const int aColW = (tl >> 1) * 4;
    const int rb = blockIdx.x * 64;

    if (blockIdx.y < 4) {
        // ===== out: BM=64, 3 sets x 64 cols, K=256, BK=16 (16 chunks) =====
        OutS& S = *(OutS*)smraw;
        const int cb = blockIdx.y * 64;

        float C[3][2][2][4];
#pragma unroll
        for (int s = 0; s < 3; s++)
#pragma unroll
            for (int mi = 0; mi < 2; mi++)
#pragma unroll
                for (int ni = 0; ni < 2; ni++)
#pragma unroll
                    for (int e = 0; e < 4; e++) C[s][mi][ni][e] = 0.f;

        auto issue = [&](int kc, int buf) {
            if (t < 128) {
                int r = t >> 1, c = (t & 1) * 4;
                cpa16(su(&S.As[buf][r][c]),
                      g_bxout + (size_t)(rb + r) * 128 + kc * 8 + c);
            }
#pragma unroll
            for (int i = 0; i < 2; i++) {
                int idx = t + i * 256;
                if (idx < 384) {
                    int s = idx >> 7, rem = idx & 127, r = rem >> 3, c = rem & 7;
                    cpa16(su(&S.Bs[buf][s][r][c * 4]),
                          g_bWo + (size_t)(kc * 16 + r) * 384 + ((s * 256 + cb) >> 1) + c * 4);
                }
            }
            CPA_COMMIT;
        };
        issue(0, 0); issue(1, 1);
        for (int kc = 0; kc < 16; kc++) {
            const int buf = kc % 3;
            CPA_WAIT_PIPE(kc, 15); __syncthreads();
            if (kc < 14) issue(kc + 2, (kc + 2) % 3);
            unsigned a[2][4], bfr[3][4];
#pragma unroll
            for (int mi = 0; mi < 2; mi++)
                ldsm4(a[mi], su(&S.As[buf][wm * 32 + mi * 16 + aRow][aColW]));
#pragma unroll
            for (int s = 0; s < 3; s++)
                ldsm4t(bfr[s], su(&S.Bs[buf][s][aRow][wn * 8 + aColW]));
#pragma unroll
            for (int s = 0; s < 3; s++)
#pragma unroll
                for (int mi = 0; mi < 2; mi++)
#pragma unroll
                    for (int ni = 0; ni < 2; ni++)
                        mma_bf16(C[s][mi][ni], a[mi], &bfr[s][ni * 2]);
        }
        // staged coalesced epilogue: two passes over mi; stage [3][32][66]
        float (*stg)[32][66] = (float(*)[32][66])smraw;   // 25344 B <= 29952
        for (int mi = 0; mi < 2; mi++) {
            __syncthreads();
#pragma unroll
            for (int s = 0; s < 3; s++)
#pragma unroll
                for (int ni = 0; ni < 2; ni++) {
                    int ur = wm * 16 + g;
                    int uc = wn * 16 + ni * 8 + 2 * tg;
                    stg[s][ur][uc]       = C[s][mi][ni][0];
                    stg[s][ur][uc + 1]   = C[s][mi][ni][1];
                    stg[s][ur + 8][uc]   = C[s][mi][ni][2];
                    stg[s][ur + 8][uc + 1] = C[s][mi][ni][3];
                }
            __syncthreads();
            // warp-per-row coalesced combine (32 stage rows, 64 cols)
            for (int u = wp; u < 32; u += 8) {
                int grow = rb + (u >> 4) * 32 + mi * 16 + (u & 15);
                int col  = cb + lane * 2;
                float2 vd = *(const float2*)(g_vd + (size_t)grow * 256 + col);
                float2 vn = *(const float2*)(g_vn + (size_t)grow * 256 + col);
                float2 o0 = *(const float2*)&stg[0][u][lane * 2];
                float2 o1 = *(const float2*)&stg[1][u][lane * 2];
                float2 o2 = *(const float2*)&stg[2][u][lane * 2];
                float2 b0 = *(const float2*)(bo + col);
                float2 b1 = *(const float2*)(bo + 256 + col);
                float2 b2 = *(const float2*)(bo + 512 + col);
                float rx = vd.x * (o0.x + b0.x) + vn.x * (o1.x + b1.x) + (o2.x + b2.x);
                float ry = vd.y * (o0.y + b0.y) + vn.y * (o1.y + b1.y) + (o2.y + b2.y);
                *(float2*)(out + (size_t)grow * 1024 + col) = make_float2(rx, ry);
            }
        }
    } else {
        // ===== gate: BM=64, BN=64, K=512, BK=32 (16 chunks) =====
        GateS& S = *(GateS*)smraw;
        const int cb = (blockIdx.y - 4) * 64;
        const float adv = *alpha_dot, anv = *alpha_norm;

        float C[2][2][2][4];
#pragma unroll
        for (int p = 0; p < 2; p++)
#pragma unroll
            for (int mi = 0; mi < 2; mi++)
#pragma unroll
                for (int ni = 0; ni < 2; ni++)
#pragma unroll
                    for (int e = 0; e < 4; e++) C[p][mi][ni][e] = 0.f;

        const int ar = t >> 2, ac = (t & 3) * 4;
        auto issue = [&](int kc, int buf) {
            const unsigned* srcA = (kc < 8) ? g_bvd : g_bvn;
            cpa16(su(&S.As[buf][ar][ac]),
                  srcA + (size_t)(rb + ar) * 128 + (kc & 7) * 16 + ac);
            {
                int r = t >> 3, c = t & 7;
                cpa16(su(&S.Bs[buf][r][c * 4]),
                      g_bWg + (size_t)(kc * 32 + r) * 128 + (cb >> 1) + c * 4);
            }
            CPA_COMMIT;
        };
        issue(0, 0); issue(1, 1);
        for (int kc = 0; kc < 16; kc++) {
            const int buf = kc % 3;
            const int p = kc >> 3;
            CPA_WAIT_PIPE(kc, 15); __syncthreads();
            if (kc < 14) issue(kc + 2, (kc + 2) % 3);
#pragma unroll
            for (int kk = 0; kk < 32; kk += 16) {
                const int kkW = kk >> 1;
                unsigned a[2][4], bfr[4];
#pragma unroll
                for (int mi = 0; mi < 2; mi++)
                    ldsm4(a[mi], su(&S.As[buf][wm * 32 + mi * 16 + aRow][aColW + kkW]));
                ldsm4t(bfr, su(&S.Bs[buf][kk + aRow][wn * 8 + aColW]));
#pragma unroll
                for (int mi = 0; mi < 2; mi++)
#pragma unroll
                    for (int ni = 0; ni < 2; ni++)
                        mma_bf16(C[p][mi][ni], a[mi], &bfr[ni * 2]);
            }
        }
        // staged coalesced epilogue: gate values -> smem [64][66]
        __syncthreads();
        float (*gstg)[66] = (float(*)[66])smraw;          // 16896 B <= 29184
#pragma unroll
        for (int mi = 0; mi < 2; mi++)
#pragma unroll
            for (int ni = 0; ni < 2; ni++) {
                int uc = wn * 16 + ni * 8 + 2 * tg;
                float bg0 = bg[cb + uc], bg1 = bg[cb + uc + 1];
#pragma unroll
                for (int hf = 0; hf < 2; hf++) {
                    int ur = wm * 32 + mi * 16 + g + hf * 8;
                    int e = hf * 2;
                    float z0 = adv * C[0][mi][ni][e]   + anv * C[1][mi][ni][e]   + bg0;
                    float z1 = adv * C[0][mi][ni][e+1] + anv * C[1][mi][ni][e+1] + bg1;
                    gstg[ur][uc]     = 1.f / (1.f + expf(-z0));
                    gstg[ur][uc + 1] = 1.f / (1.f + expf(-z1));
                }
            }
        __syncthreads();
        // warp-per-row coalesced combine over 3 channels
        for (int u = wp; u < 64; u += 8) {
            int grow = rb + u;
            int col  = cb + lane * 2;
            float2 gg = *(const float2*)&gstg[u][lane * 2];
#pragma unroll
            for (int c = 0; c < 3; c++) {
                float2 va = *(const float2*)(g_vaggr + ((size_t)grow * 3 + c) * 256 + col);
                size_t oi = ((size_t)grow * 4 + 1 + c) * 256 + col;
                float2 xv = *(const float2*)(x + oi);
                *(float2*)(out + oi) = make_float2(gg.x * va.x + xv.x, gg.y * va.y + xv.y);
            }
        }
    }
}

// ---------------- launch ----------------------------------------------------
extern "C" void kernel_launch(void* const* d_in, const int* in_sizes, int n_in,
                              void* d_out, int out_size)
{
    const float* x    = (const float*)d_in[0];
    const float* Wq   = (const float*)d_in[1];
    const float* bq   = (const float*)d_in[2];
    const float* Wk   = (const float*)d_in[3];
    const float* bk   = (const float*)d_in[4];
    const float* Wv   = (const float*)d_in[5];
    const float* bv   = (const float*)d_in[6];
    const float* Wo   = (const float*)d_in[7];
    const float* bo   = (const float*)d_in[8];
    const float* Wvec = (const float*)d_in[9];
    const float* ad   = (const float*)d_in[10];
    const float* an   = (const float*)d_in[11];
    const float* Wg   = (const float*)d_in[12];
    const float* bg   = (const float*)d_in[13];
    float* out = (float*)d_out;

    prep_bf16<<<1024, 256>>>(x, Wq, Wk, Wv, Wvec, Wo, Wg);
    proj_mma <<<384 + 1024, 256>>>(x, bq, bk, bv);
    attn_kernel<<<dim3(NN / 32, NH, BB), 128>>>(out);
    epi_mma<<<dim3(BN / 64, 8), 256>>>(x, bo, bg, ad, an, out);
}